// round 10
// baseline (speedup 1.0000x reference)
#include <cuda_runtime.h>
#include <cuda_bf16.h>
#include <cstdint>

#define B_    8
#define T_    400
#define U_    60
#define U1_   61
#define E_    256
#define H_    512
#define V_    28
#define BLANK_ 27
#define NEGF  (-1e30f)
#define LOG2E 1.4426950408889634f
#define LN2   0.6931471805599453f

// joint smem layout (bytes)
#define GSTR   516
#define DSTR   34
#define SM_G   0
#define SM_F   132096
#define SM_BF  148480
#define SM_D   181248
#define SM_BP  198656
#define JSMEM  198784

// gemm smem
#define GASTR  132
#define GEMM_SMEM (2 * 64 * GASTR * 4)
#define NB1    50                        // F-GEMM row blocks (3200/64)
#define NB2    8                         // G-GEMM row blocks (ceil(488/64))

// dp smem: 2*T*U1 floats + 128 pad (prefetch overrun)
#define DP_SMEM ((2 * T_ * U1_ + 128) * 4)

// Scratch (no cudaMalloc allowed)
__device__ float g_F[B_*T_*H_];
__device__ float g_G[B_*U1_*H_];
__device__ float g_blank[B_*T_*U1_];
__device__ float g_lab[B_*T_*U1_];

__device__ __forceinline__ float fast_tanh(float x) {
    float y; asm("tanh.approx.f32 %0, %1;" : "=f"(y) : "f"(x)); return y;
}
__device__ __forceinline__ float fast_ex2(float x) {
    float y; asm("ex2.approx.f32 %0, %1;" : "=f"(y) : "f"(x)); return y;
}
__device__ __forceinline__ float fast_lg2(float x) {
    float y; asm("lg2.approx.f32 %0, %1;" : "=f"(y) : "f"(x)); return y;
}
__device__ __forceinline__ uint32_t pack_bf16x2(float lo, float hi) {
    uint32_t r;
    asm("cvt.rn.bf16x2.f32 %0, %1, %2;" : "=r"(r) : "f"(hi), "f"(lo));
    return r;
}
__device__ __forceinline__ void mma_bf16(float& d0, float& d1, float& d2, float& d3,
                                         uint32_t a0, uint32_t a1, uint32_t a2, uint32_t a3,
                                         uint32_t b0, uint32_t b1) {
    asm("mma.sync.aligned.m16n8k16.row.col.f32.bf16.bf16.f32 "
        "{%0,%1,%2,%3}, {%4,%5,%6,%7}, {%8,%9}, {%0,%1,%2,%3};"
        : "+f"(d0), "+f"(d1), "+f"(d2), "+f"(d3)
        : "r"(a0), "r"(a1), "r"(a2), "r"(a3), "r"(b0), "r"(b1));
}

// ---------------------------------------------------------------------------
// Merged bf16 HMMA GEMM: blockIdx.y < NB1 -> F = enc@We + bf; else G = dec@Wd.
// Tile 64x64, K=256 smem-resident, 128 thr / 4 warps.
// ---------------------------------------------------------------------------
__global__ void __launch_bounds__(128)
gemm_hmma_kernel(const float* __restrict__ A1,
                 const float* __restrict__ A2,
                 const float* __restrict__ B1,
                 const float* __restrict__ B2,
                 const float* __restrict__ bias1,
                 float* __restrict__ C1,
                 float* __restrict__ C2,
                 int M1, int M2)
{
    extern __shared__ uint32_t gsm[];
    uint32_t* sA = gsm;
    uint32_t* sB = gsm + 64 * GASTR;

    const int tid  = threadIdx.x;
    const int wid  = tid >> 5;
    const int lane = tid & 31;
    const int N = H_;

    const float* A; const float* Bm; const float* bias; float* C;
    int M, mb;
    if (blockIdx.y < NB1) {
        A = A1; Bm = B1; bias = bias1; C = C1; M = M1; mb = blockIdx.y * 64;
    } else {
        A = A2; Bm = B2; bias = nullptr; C = C2; M = M2; mb = (blockIdx.y - NB1) * 64;
    }
    const int nb = blockIdx.x * 64;

    for (int i = tid; i < 64 * 64; i += 128) {
        int r  = i >> 6;
        int k4 = i & 63;
        int gm = mb + r;
        float4 v = make_float4(0.f, 0.f, 0.f, 0.f);
        if (gm < M) v = *(const float4*)(A + (size_t)gm * 256 + k4 * 4);
        sA[r * GASTR + k4 * 2]     = pack_bf16x2(v.x, v.y);
        sA[r * GASTR + k4 * 2 + 1] = pack_bf16x2(v.z, v.w);
    }
    for (int i = tid; i < 128 * 16; i += 128) {
        int k2 = i >> 4;
        int n4 = (i & 15) * 4;
        const float* p0 = Bm + (size_t)(2 * k2) * N + nb + n4;
        float4 r0 = *(const float4*)p0;
        float4 r1 = *(const float4*)(p0 + N);
        sB[(n4 + 0) * GASTR + k2] = pack_bf16x2(r0.x, r1.x);
        sB[(n4 + 1) * GASTR + k2] = pack_bf16x2(r0.y, r1.y);
        sB[(n4 + 2) * GASTR + k2] = pack_bf16x2(r0.z, r1.z);
        sB[(n4 + 3) * GASTR + k2] = pack_bf16x2(r0.w, r1.w);
    }
    __syncthreads();

    const int gr = lane >> 2;
    const int c  = lane & 3;
    const uint32_t* pa  = sA + (wid * 16 + gr) * GASTR;
    const uint32_t* pa8 = pa + 8 * GASTR;
    const uint32_t* pbn = sB + gr * GASTR;

    float d0[8], d1[8], d2[8], d3[8];
    #pragma unroll
    for (int nt = 0; nt < 8; nt++) { d0[nt] = d1[nt] = d2[nt] = d3[nt] = 0.f; }

    #pragma unroll 4
    for (int ch = 0; ch < 16; ch++) {
        int k2b = ch * 8;
        uint32_t a0 = pa[k2b + c];
        uint32_t a1 = pa8[k2b + c];
        uint32_t a2 = pa[k2b + 4 + c];
        uint32_t a3 = pa8[k2b + 4 + c];
        #pragma unroll
        for (int nt = 0; nt < 8; nt++) {
            uint32_t b0 = pbn[nt * 8 * GASTR + k2b + c];
            uint32_t b1 = pbn[nt * 8 * GASTR + k2b + 4 + c];
            mma_bf16(d0[nt], d1[nt], d2[nt], d3[nt], a0, a1, a2, a3, b0, b1);
        }
    }

    int gm0 = mb + wid * 16 + gr;
    int gm1 = gm0 + 8;
    #pragma unroll
    for (int nt = 0; nt < 8; nt++) {
        int gn = nb + nt * 8 + 2 * c;
        float bb0 = bias ? bias[gn]     : 0.f;
        float bb1 = bias ? bias[gn + 1] : 0.f;
        if (gm0 < M) *(float2*)(C + (size_t)gm0 * N + gn) = make_float2(d0[nt] + bb0, d1[nt] + bb1);
        if (gm1 < M) *(float2*)(C + (size_t)gm1 * N + gn) = make_float2(d2[nt] + bb0, d3[nt] + bb1);
    }
}

// ---------------------------------------------------------------------------
// HMMA joint kernel. B-fragments relaid as [ch][lane][8] -> 2x LDS.128/chunk.
// ---------------------------------------------------------------------------
__global__ void __launch_bounds__(256)
joint_hmma_kernel(const float* __restrict__ Wp,
                  const float* __restrict__ bp,
                  const int*  __restrict__ targets)
{
    extern __shared__ char smraw[];
    float*    sG  = (float*)(smraw + SM_G);
    float*    sF  = (float*)(smraw + SM_F);
    uint32_t* sBf = (uint32_t*)(smraw + SM_BF);
    float*    sD  = (float*)(smraw + SM_D);
    float*    sBp = (float*)(smraw + SM_BP);

    const int b     = blockIdx.y;
    const int tbase = blockIdx.x * 8;
    const int tid   = threadIdx.x;
    const int wid   = tid >> 5;
    const int lane  = tid & 31;

    const float* Fb = g_F + (size_t)(b * T_ + tbase) * H_;
    const float* Gb = g_G + (size_t)b * U1_ * H_;

    if (tid < V_) sBp[tid] = bp[tid];

    for (int i = tid; i < 64 * (H_ / 4); i += 256) {
        int r = i >> 7;
        int cc = (i & 127) << 2;
        float4 v4 = make_float4(0.f, 0.f, 0.f, 0.f);
        if (r < U1_) v4 = *(const float4*)(Gb + (size_t)r * H_ + cc);
        *(float4*)&sG[r * GSTR + cc] = v4;
    }
    for (int i = tid; i < 8 * (H_ / 4); i += 256) {
        int r = i >> 7;
        int cc = (i & 127) << 2;
        *(float4*)&sF[r * H_ + cc] = *(const float4*)(Fb + (size_t)r * H_ + cc);
    }
    // B fragments: sBf[ch*256 + lane*8 + nt*2 + j]
    for (int i = tid; i < 32 * 4 * 32; i += 256) {
        int ch = i >> 7;
        int nt = (i >> 5) & 3;
        int l  = i & 31;
        int kA = ch * 16 + 2 * (l & 3);
        int n  = nt * 8 + (l >> 2);
        uint32_t b0 = 0, b1 = 0;
        if (n < V_) {
            b0 = pack_bf16x2(Wp[(size_t)kA * V_ + n],       Wp[(size_t)(kA + 1) * V_ + n]);
            b1 = pack_bf16x2(Wp[(size_t)(kA + 8) * V_ + n], Wp[(size_t)(kA + 9) * V_ + n]);
        }
        sBf[ch * 256 + l * 8 + nt * 2 + 0] = b0;
        sBf[ch * 256 + l * 8 + nt * 2 + 1] = b1;
    }
    __syncthreads();

    const int s    = wid & 3;
    const int tsub = wid >> 2;
    const int u0   = s * 16;
    const int gr    = lane >> 2;
    const int cbase = (lane & 3) * 2;

    const float* gRowA = sG + (u0 + gr) * GSTR;
    const float* gRowB = sG + (u0 + gr + 8) * GSTR;
    const uint4* bfL = (const uint4*)(sBf + lane * 8);
    float* sDw = sD + wid * (16 * DSTR);

    #pragma unroll 1
    for (int it = 0; it < 4; it++) {
        const int tloc = tsub * 4 + it;
        const float* fRow = sF + tloc * H_;

        float d0[4], d1[4], d2[4], d3[4];
        #pragma unroll
        for (int nt = 0; nt < 4; nt++) { d0[nt] = d1[nt] = d2[nt] = d3[nt] = 0.f; }

        #pragma unroll 2
        for (int ch = 0; ch < 32; ch++) {
            int k = ch * 16 + cbase;
            float2 fA  = *(const float2*)(fRow  + k);
            float2 fB  = *(const float2*)(fRow  + k + 8);
            float2 gAa = *(const float2*)(gRowA + k);
            float2 gBa = *(const float2*)(gRowA + k + 8);
            float2 gAb = *(const float2*)(gRowB + k);
            float2 gBb = *(const float2*)(gRowB + k + 8);
            uint32_t a0 = pack_bf16x2(fast_tanh(fA.x + gAa.x), fast_tanh(fA.y + gAa.y));
            uint32_t a1 = pack_bf16x2(fast_tanh(fA.x + gAb.x), fast_tanh(fA.y + gAb.y));
            uint32_t a2 = pack_bf16x2(fast_tanh(fB.x + gBa.x), fast_tanh(fB.y + gBa.y));
            uint32_t a3 = pack_bf16x2(fast_tanh(fB.x + gBb.x), fast_tanh(fB.y + gBb.y));
            uint4 w0 = bfL[ch * 64 + 0];      // nt0: x,y  nt1: z,w
            uint4 w1 = bfL[ch * 64 + 1];      // nt2: x,y  nt3: z,w
            mma_bf16(d0[0], d1[0], d2[0], d3[0], a0, a1, a2, a3, w0.x, w0.y);
            mma_bf16(d0[1], d1[1], d2[1], d3[1], a0, a1, a2, a3, w0.z, w0.w);
            mma_bf16(d0[2], d1[2], d2[2], d3[2], a0, a1, a2, a3, w1.x, w1.y);
            mma_bf16(d0[3], d1[3], d2[3], d3[3], a0, a1, a2, a3, w1.z, w1.w);
        }

        #pragma unroll
        for (int nt = 0; nt < 4; nt++) {
            int cc = nt * 8 + cbase;
            *(float2*)&sDw[gr * DSTR + cc]       = make_float2(d0[nt], d1[nt]);
            *(float2*)&sDw[(gr + 8) * DSTR + cc] = make_float2(d2[nt], d3[nt]);
        }
        __syncwarp();

        if (lane < 16) {
            int u = u0 + lane;
            if (u < U1_) {
                int t = tbase + tloc;
                float logits[V_];
                float m = -1e30f;
                #pragma unroll
                for (int v = 0; v < V_; v++) {
                    logits[v] = sDw[lane * DSTR + v] + sBp[v];
                    m = fmaxf(m, logits[v]);
                }
                float ssum = 0.f;
                #pragma unroll
                for (int v = 0; v < V_; v++) ssum += fast_ex2((logits[v] - m) * LOG2E);
                float lse = m + fast_lg2(ssum) * LN2;

                int tgt = (u < U_) ? targets[b * U_ + u] : 0;
                float lv = logits[0];
                #pragma unroll
                for (int v = 1; v < V_; v++)
                    if (v == tgt) lv = logits[v];

                size_t idx = (size_t)(b * T_ + t) * U1_ + u;
                g_blank[idx] = logits[BLANK_] - lse;
                if (u < U_) g_lab[idx] = lv - lse;
            }
        }
        __syncwarp();
    }
}

// ---------------------------------------------------------------------------
// Forward DP: phase-split wavefront, 2 shfls/step (wrap-shfl for hi neighbor).
// ---------------------------------------------------------------------------
__global__ void dp_kernel(const int* __restrict__ t_lens,
                          const int* __restrict__ u_lens,
                          float* __restrict__ out)
{
    extern __shared__ float sm[];
    float* sB = sm;
    float* sL = sm + T_ * U1_;

    int b   = blockIdx.x;
    int tid = threadIdx.x;

    const float4* srcB = (const float4*)(g_blank + (size_t)b * T_ * U1_);
    const float4* srcL = (const float4*)(g_lab   + (size_t)b * T_ * U1_);
    const int n4 = T_ * U1_ / 4;
    for (int i = tid; i < n4; i += 1024) {
        float4 vb = srcB[i];
        float4 vl = srcL[i];
        vb.x *= LOG2E; vb.y *= LOG2E; vb.z *= LOG2E; vb.w *= LOG2E;
        vl.x *= LOG2E; vl.y *= LOG2E; vl.z *= LOG2E; vl.w *= LOG2E;
        ((float4*)sB)[i] = vb;
        ((float4*)sL)[i] = vl;
    }
    __syncthreads();
    if (tid >= 32) return;

    const int lane = tid;
    const int Tl = t_lens[b], Ul = u_lens[b];
    const int dcap = (Tl - 1) + Ul;          // >= 229 always
    const bool cap_lo = (Ul < 32) && (lane == Ul);
    const bool cap_hi = (Ul >= 32) && (lane == Ul - 32);
    const int srcl = (lane + 31) & 31;

    const int u_lo = lane;
    const int u_hi = lane + 32;
    const int ulo_m1 = max(u_lo - 1, 0);
    const int uhi_c  = min(u_hi, U1_ - 1);
    const int uhi_m1 = min(u_hi - 1, U1_ - 1);

    float a_lo = (lane == 0) ? 0.f : NEGF;
    float a_hi = NEGF;
    float res  = 0.f;

    // ---- phase 1: d in [1,63], clamped, no capture ----
    for (int d = 1; d <= 63; d++) {
        float p_lo = __shfl_up_sync(0xffffffffu, a_lo, 1);
        p_lo = (lane == 0) ? NEGF : p_lo;
        float yh   = (lane == 31) ? a_lo : a_hi;
        float p_hi = __shfl_sync(0xffffffffu, yh, srcl);

        int t  = d - u_lo;
        int i1 = min(max(t - 1, 0), T_ - 1);
        int i2 = min(max(t, 0), T_ - 1);
        float v1 = a_lo + sB[i1 * U1_ + u_lo];
        float v2 = p_lo + sL[i2 * U1_ + ulo_m1];
        float mx = fmaxf(v1, v2), mn = fminf(v1, v2);
        a_lo = mx + fast_lg2(1.f + fast_ex2(mn - mx));

        int th = d - u_hi;
        int j1 = min(max(th - 1, 0), T_ - 1);
        int j2 = min(max(th, 0), T_ - 1);
        float w1 = a_hi + sB[j1 * U1_ + uhi_c];
        float w2 = p_hi + sL[j2 * U1_ + uhi_m1];
        float mxh = fmaxf(w1, w2), mnh = fminf(w1, w2);
        a_hi = mxh + fast_lg2(1.f + fast_ex2(mnh - mxh));
    }

    // ---- phase 2: d in [64,399], clamp-free, prefetched ----
    {
        int ob_lo = (63 - u_lo) * U1_ + u_lo;
        int ol_lo = (64 - u_lo) * U1_ + ulo_m1;
        int ob_hi = (63 - u_hi) * U1_ + uhi_c;
        int ol_hi = (64 - u_hi) * U1_ + uhi_m1;

        float Blo = sB[ob_lo], Llo = sL[ol_lo];
        float Bhi = sB[ob_hi], Lhi = sL[ol_hi];

        #pragma unroll 2
        for (int d = 64; d <= 399; d++) {
            ob_lo += U1_; ol_lo += U1_; ob_hi += U1_; ol_hi += U1_;
            float nBlo = sB[ob_lo];
            float nLlo = sL[ol_lo];
            float nBhi = sB[ob_hi];
            float nLhi = sL[ol_hi];

            float p_lo = __shfl_up_sync(0xffffffffu, a_lo, 1);
            p_lo = (lane == 0) ? NEGF : p_lo;
            float yh   = (lane == 31) ? a_lo : a_hi;
            float p_hi = __shfl_sync(0xffffffffu, yh, srcl);

            float v1 = a_lo + Blo;
            float v2 = p_lo + Llo;
            float mx = fmaxf(v1, v2), mn = fminf(v1, v2);
            float n_lo = mx + fast_lg2(1.f + fast_ex2(mn - mx));

            float w1 = a_hi + Bhi;
            float w2 = p_hi + Lhi;
            float mxh = fmaxf(w1, w2), mnh = fminf(w1, w2);
            float n_hi = mxh + fast_lg2(1.f + fast_ex2(mnh - mxh));

            bool hit = (d == dcap);
            res = (hit && cap_lo) ? n_lo : res;
            res = (hit && cap_hi) ? n_hi : res;
            a_lo = n_lo;
            a_hi = n_hi;
            Blo = nBlo; Llo = nLlo; Bhi = nBhi; Lhi = nLhi;
        }
    }

    // ---- phase 3: d in [400,459], clamped ----
    for (int d = 400; d <= 459; d++) {
        float p_lo = __shfl_up_sync(0xffffffffu, a_lo, 1);
        p_lo = (lane == 0) ? NEGF : p_lo;
        float yh   = (lane == 31) ? a_lo : a_hi;
        float p_hi = __shfl_sync(0xffffffffu, yh, srcl);

        int t  = d - u_lo;
        int i1 = min(max(t - 1, 0), T_ - 1);
        int i2 = min(max(t, 0), T_ - 1);
        float v1 = a_lo + sB[i1 * U1_ + u_lo];
        float v2 = p_lo + sL[i2 * U1_ + ulo_m1];
        float mx = fmaxf(v1, v2), mn = fminf(v1, v2);
        float n_lo = mx + fast_lg2(1.f + fast_ex2(mn - mx));

        int th = d - u_hi;
        int j1 = min(max(th - 1, 0), T_ - 1);
        int j2 = min(max(th, 0), T_ - 1);
        float w1 = a_hi + sB[j1 * U1_ + uhi_c];
        float w2 = p_hi + sL[j2 * U1_ + uhi_m1];
        float mxh = fmaxf(w1, w2), mnh = fminf(w1, w2);
        float n_hi = mxh + fast_lg2(1.f + fast_ex2(mnh - mxh));

        bool hit = (d == dcap);
        res = (hit && cap_lo) ? n_lo : res;
        res = (hit && cap_hi) ? n_hi : res;
        a_lo = n_lo;
        a_hi = n_hi;
    }

    if (cap_lo || cap_hi) {
        float blank_fin = g_blank[(size_t)b * T_ * U1_ + (size_t)(Tl - 1) * U1_ + Ul];
        out[b] = -(res * LN2 + blank_fin);
    }
}

// ---------------------------------------------------------------------------
extern "C" void kernel_launch(void* const* d_in, const int* in_sizes, int n_in,
                              void* d_out, int out_size)
{
    const float* enc     = (const float*)d_in[0];
    const float* dec     = (const float*)d_in[1];
    const float* We      = (const float*)d_in[2];
    const float* Wd      = (const float*)d_in[3];
    const float* bf      = (const float*)d_in[4];
    const float* Wp      = (const float*)d_in[5];
    const float* bp      = (const float*)d_in[6];
    const int*   targets = (const int*)d_in[7];
    const int*   t_lens  = (const int*)d_in[8];
    const int*   u_lens  = (const int*)d_in[9];
    float* out = (float*)d_out;

    float *pF = nullptr, *pG = nullptr;
    cudaGetSymbolAddress((void**)&pF, g_F);
    cudaGetSymbolAddress((void**)&pG, g_G);

    static bool attr_set = false;
    if (!attr_set) {
        cudaFuncSetAttribute(dp_kernel,
                             cudaFuncAttributeMaxDynamicSharedMemorySize, DP_SMEM);
        cudaFuncSetAttribute(joint_hmma_kernel,
                             cudaFuncAttributeMaxDynamicSharedMemorySize, JSMEM);
        cudaFuncSetAttribute(gemm_hmma_kernel,
                             cudaFuncAttributeMaxDynamicSharedMemorySize, GEMM_SMEM);
        attr_set = true;
    }

    gemm_hmma_kernel<<<dim3(H_ / 64, NB1 + NB2), 128, GEMM_SMEM>>>(
        enc, dec, We, Wd, bf, pF, pG, B_ * T_, B_ * U1_);
    joint_hmma_kernel<<<dim3(T_ / 8, B_), 256, JSMEM>>>(Wp, bp, targets);
    dp_kernel<<<B_, 1024, DP_SMEM>>>(t_lens, u_lens, out);
}

// round 11
// speedup vs baseline: 1.0439x; 1.0439x over previous
#include <cuda_runtime.h>
#include <cuda_bf16.h>
#include <cstdint>

#define B_    8
#define T_    400
#define U_    60
#define U1_   61
#define E_    256
#define H_    512
#define V_    28
#define BLANK_ 27
#define NEGF  (-1e30f)
#define LOG2E 1.4426950408889634f
#define LN2   0.6931471805599453f

// joint smem layout (bytes)
#define GSTR   516
#define DSTR   34
#define SM_G   0
#define SM_F   132096
#define SM_BF  148480
#define SM_D   181248
#define SM_BP  198656
#define JSMEM  198784

// gemm smem
#define GASTR  132
#define GEMM_SMEM (2 * 64 * GASTR * 4)
#define NB1    50
#define NB2    8

// dp smem: 2*T*U1 floats + 128 pad (prefetch overrun)
#define DP_SMEM ((2 * T_ * U1_ + 128) * 4)

// Scratch (no cudaMalloc allowed)
__device__ float g_F[B_*T_*H_];
__device__ float g_G[B_*U1_*H_];
__device__ float g_blank[B_*T_*U1_];
__device__ float g_lab[B_*T_*U1_];

__device__ __forceinline__ float fast_tanh(float x) {
    float y; asm("tanh.approx.f32 %0, %1;" : "=f"(y) : "f"(x)); return y;
}
__device__ __forceinline__ float fast_ex2(float x) {
    float y; asm("ex2.approx.f32 %0, %1;" : "=f"(y) : "f"(x)); return y;
}
__device__ __forceinline__ float fast_lg2(float x) {
    float y; asm("lg2.approx.f32 %0, %1;" : "=f"(y) : "f"(x)); return y;
}
__device__ __forceinline__ uint32_t pack_bf16x2(float lo, float hi) {
    uint32_t r;
    asm("cvt.rn.bf16x2.f32 %0, %1, %2;" : "=r"(r) : "f"(hi), "f"(lo));
    return r;
}
__device__ __forceinline__ void mma_bf16(float& d0, float& d1, float& d2, float& d3,
                                         uint32_t a0, uint32_t a1, uint32_t a2, uint32_t a3,
                                         uint32_t b0, uint32_t b1) {
    asm("mma.sync.aligned.m16n8k16.row.col.f32.bf16.bf16.f32 "
        "{%0,%1,%2,%3}, {%4,%5,%6,%7}, {%8,%9}, {%0,%1,%2,%3};"
        : "+f"(d0), "+f"(d1), "+f"(d2), "+f"(d3)
        : "r"(a0), "r"(a1), "r"(a2), "r"(a3), "r"(b0), "r"(b1));
}

// ---------------------------------------------------------------------------
// Merged bf16 HMMA GEMM, 256 threads (8 warps): blockIdx.y < NB1 -> F; else G.
// Tile 64x64, K=256 smem-resident. Warp w: m-strip (w&3)*16, n-half (w>>2)*32.
// ---------------------------------------------------------------------------
__global__ void __launch_bounds__(256)
gemm_hmma_kernel(const float* __restrict__ A1,
                 const float* __restrict__ A2,
                 const float* __restrict__ B1,
                 const float* __restrict__ B2,
                 const float* __restrict__ bias1,
                 float* __restrict__ C1,
                 float* __restrict__ C2,
                 int M1, int M2)
{
    extern __shared__ uint32_t gsm[];
    uint32_t* sA = gsm;
    uint32_t* sB = gsm + 64 * GASTR;

    const int tid  = threadIdx.x;
    const int wid  = tid >> 5;
    const int lane = tid & 31;
    const int N = H_;

    const float* A; const float* Bm; const float* bias; float* C;
    int M, mb;
    if (blockIdx.y < NB1) {
        A = A1; Bm = B1; bias = bias1; C = C1; M = M1; mb = blockIdx.y * 64;
    } else {
        A = A2; Bm = B2; bias = nullptr; C = C2; M = M2; mb = (blockIdx.y - NB1) * 64;
    }
    const int nb = blockIdx.x * 64;

    // stage A: 64 rows x 64 float4 (16 per thread)
    for (int i = tid; i < 64 * 64; i += 256) {
        int r  = i >> 6;
        int k4 = i & 63;
        int gm = mb + r;
        float4 v = make_float4(0.f, 0.f, 0.f, 0.f);
        if (gm < M) v = *(const float4*)(A + (size_t)gm * 256 + k4 * 4);
        sA[r * GASTR + k4 * 2]     = pack_bf16x2(v.x, v.y);
        sA[r * GASTR + k4 * 2 + 1] = pack_bf16x2(v.z, v.w);
    }
    // stage B: 128 k2 x 16 n4-groups (8 per thread)
    for (int i = tid; i < 128 * 16; i += 256) {
        int k2 = i >> 4;
        int n4 = (i & 15) * 4;
        const float* p0 = Bm + (size_t)(2 * k2) * N + nb + n4;
        float4 r0 = *(const float4*)p0;
        float4 r1 = *(const float4*)(p0 + N);
        sB[(n4 + 0) * GASTR + k2] = pack_bf16x2(r0.x, r1.x);
        sB[(n4 + 1) * GASTR + k2] = pack_bf16x2(r0.y, r1.y);
        sB[(n4 + 2) * GASTR + k2] = pack_bf16x2(r0.z, r1.z);
        sB[(n4 + 3) * GASTR + k2] = pack_bf16x2(r0.w, r1.w);
    }
    __syncthreads();

    const int gr = lane >> 2;
    const int c  = lane & 3;
    const int mrow  = (wid & 3) * 16;
    const int nhalf = (wid >> 2) * 4;     // n-tile base: 0 or 4
    const uint32_t* pa  = sA + (mrow + gr) * GASTR;
    const uint32_t* pa8 = pa + 8 * GASTR;
    const uint32_t* pbn = sB + gr * GASTR + nhalf * 8 * GASTR;

    float d0[4], d1[4], d2[4], d3[4];
    #pragma unroll
    for (int nt = 0; nt < 4; nt++) { d0[nt] = d1[nt] = d2[nt] = d3[nt] = 0.f; }

    #pragma unroll 4
    for (int ch = 0; ch < 16; ch++) {
        int k2b = ch * 8;
        uint32_t a0 = pa[k2b + c];
        uint32_t a1 = pa8[k2b + c];
        uint32_t a2 = pa[k2b + 4 + c];
        uint32_t a3 = pa8[k2b + 4 + c];
        #pragma unroll
        for (int nt = 0; nt < 4; nt++) {
            uint32_t b0 = pbn[nt * 8 * GASTR + k2b + c];
            uint32_t b1 = pbn[nt * 8 * GASTR + k2b + 4 + c];
            mma_bf16(d0[nt], d1[nt], d2[nt], d3[nt], a0, a1, a2, a3, b0, b1);
        }
    }

    int gm0 = mb + mrow + gr;
    int gm1 = gm0 + 8;
    #pragma unroll
    for (int nt = 0; nt < 4; nt++) {
        int gn = nb + (nhalf + nt) * 8 + 2 * c;
        float bb0 = bias ? bias[gn]     : 0.f;
        float bb1 = bias ? bias[gn + 1] : 0.f;
        if (gm0 < M) *(float2*)(C + (size_t)gm0 * N + gn) = make_float2(d0[nt] + bb0, d1[nt] + bb1);
        if (gm1 < M) *(float2*)(C + (size_t)gm1 * N + gn) = make_float2(d2[nt] + bb0, d3[nt] + bb1);
    }
}

// ---------------------------------------------------------------------------
// HMMA joint kernel (R10: uint4 B-fragment loads).
// ---------------------------------------------------------------------------
__global__ void __launch_bounds__(256)
joint_hmma_kernel(const float* __restrict__ Wp,
                  const float* __restrict__ bp,
                  const int*  __restrict__ targets)
{
    extern __shared__ char smraw[];
    float*    sG  = (float*)(smraw + SM_G);
    float*    sF  = (float*)(smraw + SM_F);
    uint32_t* sBf = (uint32_t*)(smraw + SM_BF);
    float*    sD  = (float*)(smraw + SM_D);
    float*    sBp = (float*)(smraw + SM_BP);

    const int b     = blockIdx.y;
    const int tbase = blockIdx.x * 8;
    const int tid   = threadIdx.x;
    const int wid   = tid >> 5;
    const int lane  = tid & 31;

    const float* Fb = g_F + (size_t)(b * T_ + tbase) * H_;
    const float* Gb = g_G + (size_t)b * U1_ * H_;

    if (tid < V_) sBp[tid] = bp[tid];

    for (int i = tid; i < 64 * (H_ / 4); i += 256) {
        int r = i >> 7;
        int cc = (i & 127) << 2;
        float4 v4 = make_float4(0.f, 0.f, 0.f, 0.f);
        if (r < U1_) v4 = *(const float4*)(Gb + (size_t)r * H_ + cc);
        *(float4*)&sG[r * GSTR + cc] = v4;
    }
    for (int i = tid; i < 8 * (H_ / 4); i += 256) {
        int r = i >> 7;
        int cc = (i & 127) << 2;
        *(float4*)&sF[r * H_ + cc] = *(const float4*)(Fb + (size_t)r * H_ + cc);
    }
    for (int i = tid; i < 32 * 4 * 32; i += 256) {
        int ch = i >> 7;
        int nt = (i >> 5) & 3;
        int l  = i & 31;
        int kA = ch * 16 + 2 * (l & 3);
        int n  = nt * 8 + (l >> 2);
        uint32_t b0 = 0, b1 = 0;
        if (n < V_) {
            b0 = pack_bf16x2(Wp[(size_t)kA * V_ + n],       Wp[(size_t)(kA + 1) * V_ + n]);
            b1 = pack_bf16x2(Wp[(size_t)(kA + 8) * V_ + n], Wp[(size_t)(kA + 9) * V_ + n]);
        }
        sBf[ch * 256 + l * 8 + nt * 2 + 0] = b0;
        sBf[ch * 256 + l * 8 + nt * 2 + 1] = b1;
    }
    __syncthreads();

    const int s    = wid & 3;
    const int tsub = wid >> 2;
    const int u0   = s * 16;
    const int gr    = lane >> 2;
    const int cbase = (lane & 3) * 2;

    const float* gRowA = sG + (u0 + gr) * GSTR;
    const float* gRowB = sG + (u0 + gr + 8) * GSTR;
    const uint4* bfL = (const uint4*)(sBf + lane * 8);
    float* sDw = sD + wid * (16 * DSTR);

    #pragma unroll 1
    for (int it = 0; it < 4; it++) {
        const int tloc = tsub * 4 + it;
        const float* fRow = sF + tloc * H_;

        float d0[4], d1[4], d2[4], d3[4];
        #pragma unroll
        for (int nt = 0; nt < 4; nt++) { d0[nt] = d1[nt] = d2[nt] = d3[nt] = 0.f; }

        #pragma unroll 2
        for (int ch = 0; ch < 32; ch++) {
            int k = ch * 16 + cbase;
            float2 fA  = *(const float2*)(fRow  + k);
            float2 fB  = *(const float2*)(fRow  + k + 8);
            float2 gAa = *(const float2*)(gRowA + k);
            float2 gBa = *(const float2*)(gRowA + k + 8);
            float2 gAb = *(const float2*)(gRowB + k);
            float2 gBb = *(const float2*)(gRowB + k + 8);
            uint32_t a0 = pack_bf16x2(fast_tanh(fA.x + gAa.x), fast_tanh(fA.y + gAa.y));
            uint32_t a1 = pack_bf16x2(fast_tanh(fA.x + gAb.x), fast_tanh(fA.y + gAb.y));
            uint32_t a2 = pack_bf16x2(fast_tanh(fB.x + gBa.x), fast_tanh(fB.y + gBa.y));
            uint32_t a3 = pack_bf16x2(fast_tanh(fB.x + gBb.x), fast_tanh(fB.y + gBb.y));
            uint4 w0 = bfL[ch * 64 + 0];
            uint4 w1 = bfL[ch * 64 + 1];
            mma_bf16(d0[0], d1[0], d2[0], d3[0], a0, a1, a2, a3, w0.x, w0.y);
            mma_bf16(d0[1], d1[1], d2[1], d3[1], a0, a1, a2, a3, w0.z, w0.w);
            mma_bf16(d0[2], d1[2], d2[2], d3[2], a0, a1, a2, a3, w1.x, w1.y);
            mma_bf16(d0[3], d1[3], d2[3], d3[3], a0, a1, a2, a3, w1.z, w1.w);
        }

        #pragma unroll
        for (int nt = 0; nt < 4; nt++) {
            int cc = nt * 8 + cbase;
            *(float2*)&sDw[gr * DSTR + cc]       = make_float2(d0[nt], d1[nt]);
            *(float2*)&sDw[(gr + 8) * DSTR + cc] = make_float2(d2[nt], d3[nt]);
        }
        __syncwarp();

        if (lane < 16) {
            int u = u0 + lane;
            if (u < U1_) {
                int t = tbase + tloc;
                float logits[V_];
                float m = -1e30f;
                #pragma unroll
                for (int v = 0; v < V_; v++) {
                    logits[v] = sDw[lane * DSTR + v] + sBp[v];
                    m = fmaxf(m, logits[v]);
                }
                float ssum = 0.f;
                #pragma unroll
                for (int v = 0; v < V_; v++) ssum += fast_ex2((logits[v] - m) * LOG2E);
                float lse = m + fast_lg2(ssum) * LN2;

                int tgt = (u < U_) ? targets[b * U_ + u] : 0;
                float lv = logits[0];
                #pragma unroll
                for (int v = 1; v < V_; v++)
                    if (v == tgt) lv = logits[v];

                size_t idx = (size_t)(b * T_ + t) * U1_ + u;
                g_blank[idx] = logits[BLANK_] - lse;
                if (u < U_) g_lab[idx] = lv - lse;
            }
        }
        __syncwarp();
    }
}

// ---------------------------------------------------------------------------
// Forward DP: phase-split wavefront, 2 shfls/step, terminates at dcap,
// stages only the rows the wavefront touches.
// ---------------------------------------------------------------------------
__global__ void dp_kernel(const int* __restrict__ t_lens,
                          const int* __restrict__ u_lens,
                          float* __restrict__ out)
{
    extern __shared__ float sm[];
    float* sB = sm;
    float* sL = sm + T_ * U1_;

    int b   = blockIdx.x;
    int tid = threadIdx.x;

    const int Tl = t_lens[b], Ul = u_lens[b];
    const int dcap = (Tl - 1) + Ul;          // in [229, 459]

    const float4* srcB = (const float4*)(g_blank + (size_t)b * T_ * U1_);
    const float4* srcL = (const float4*)(g_lab   + (size_t)b * T_ * U1_);
    const int nrows = min(T_, dcap + 2);
    const int n4 = (nrows * U1_ + 3) / 4;
    for (int i = tid; i < n4; i += 1024) {
        float4 vb = srcB[i];
        float4 vl = srcL[i];
        vb.x *= LOG2E; vb.y *= LOG2E; vb.z *= LOG2E; vb.w *= LOG2E;
        vl.x *= LOG2E; vl.y *= LOG2E; vl.z *= LOG2E; vl.w *= LOG2E;
        ((float4*)sB)[i] = vb;
        ((float4*)sL)[i] = vl;
    }
    __syncthreads();
    if (tid >= 32) return;

    const int lane = tid;
    const bool cap_lo = (Ul < 32) && (lane == Ul);
    const bool cap_hi = (Ul >= 32) && (lane == Ul - 32);
    const int srcl = (lane + 31) & 31;

    const int u_lo = lane;
    const int u_hi = lane + 32;
    const int ulo_m1 = max(u_lo - 1, 0);
    const int uhi_c  = min(u_hi, U1_ - 1);
    const int uhi_m1 = min(u_hi - 1, U1_ - 1);

    float a_lo = (lane == 0) ? 0.f : NEGF;
    float a_hi = NEGF;
    float res  = 0.f;

    // ---- phase 1: d in [1,63], clamped, no capture (dcap >= 229) ----
    for (int d = 1; d <= 63; d++) {
        float p_lo = __shfl_up_sync(0xffffffffu, a_lo, 1);
        p_lo = (lane == 0) ? NEGF : p_lo;
        float yh   = (lane == 31) ? a_lo : a_hi;
        float p_hi = __shfl_sync(0xffffffffu, yh, srcl);

        int t  = d - u_lo;
        int i1 = min(max(t - 1, 0), T_ - 1);
        int i2 = min(max(t, 0), T_ - 1);
        float v1 = a_lo + sB[i1 * U1_ + u_lo];
        float v2 = p_lo + sL[i2 * U1_ + ulo_m1];
        float mx = fmaxf(v1, v2), mn = fminf(v1, v2);
        a_lo = mx + fast_lg2(1.f + fast_ex2(mn - mx));

        int th = d - u_hi;
        int j1 = min(max(th - 1, 0), T_ - 1);
        int j2 = min(max(th, 0), T_ - 1);
        float w1 = a_hi + sB[j1 * U1_ + uhi_c];
        float w2 = p_hi + sL[j2 * U1_ + uhi_m1];
        float mxh = fmaxf(w1, w2), mnh = fminf(w1, w2);
        a_hi = mxh + fast_lg2(1.f + fast_ex2(mnh - mxh));
    }

    // ---- phase 2: d in [64, min(399,dcap)], clamp-free, prefetched ----
    {
        const int d2end = min(399, dcap);
        int ob_lo = (63 - u_lo) * U1_ + u_lo;
        int ol_lo = (64 - u_lo) * U1_ + ulo_m1;
        int ob_hi = (63 - u_hi) * U1_ + uhi_c;
        int ol_hi = (64 - u_hi) * U1_ + uhi_m1;

        float Blo = sB[ob_lo], Llo = sL[ol_lo];
        float Bhi = sB[ob_hi], Lhi = sL[ol_hi];

        #pragma unroll 2
        for (int d = 64; d <= d2end; d++) {
            ob_lo += U1_; ol_lo += U1_; ob_hi += U1_; ol_hi += U1_;
            float nBlo = sB[ob_lo];
            float nLlo = sL[ol_lo];
            float nBhi = sB[ob_hi];
            float nLhi = sL[ol_hi];

            float p_lo = __shfl_up_sync(0xffffffffu, a_lo, 1);
            p_lo = (lane == 0) ? NEGF : p_lo;
            float yh   = (lane == 31) ? a_lo : a_hi;
            float p_hi = __shfl_sync(0xffffffffu, yh, srcl);

            float v1 = a_lo + Blo;
            float v2 = p_lo + Llo;
            float mx = fmaxf(v1, v2), mn = fminf(v1, v2);
            float n_lo = mx + fast_lg2(1.f + fast_ex2(mn - mx));

            float w1 = a_hi + Bhi;
            float w2 = p_hi + Lhi;
            float mxh = fmaxf(w1, w2), mnh = fminf(w1, w2);
            float n_hi = mxh + fast_lg2(1.f + fast_ex2(mnh - mxh));

            bool hit = (d == dcap);
            res = (hit && cap_lo) ? n_lo : res;
            res = (hit && cap_hi) ? n_hi : res;
            a_lo = n_lo;
            a_hi = n_hi;
            Blo = nBlo; Llo = nLlo; Bhi = nBhi; Lhi = nLhi;
        }
    }

    // ---- phase 3: d in [400, dcap], clamped (only if dcap >= 400) ----
    for (int d = 400; d <= dcap; d++) {
        float p_lo = __shfl_up_sync(0xffffffffu, a_lo, 1);
        p_lo = (lane == 0) ? NEGF : p_lo;
        float yh   = (lane == 31) ? a_lo : a_hi;
        float p_hi = __shfl_sync(0xffffffffu, yh, srcl);

        int t  = d - u_lo;
        int i1 = min(max(t - 1, 0), T_ - 1);
        int i2 = min(max(t, 0), T_ - 1);
        float v1 = a_lo + sB[i1 * U1_ + u_lo];
        float v2 = p_lo + sL[i2 * U1_ + ulo_m1];
        float mx = fmaxf(v1, v2), mn = fminf(v1, v2);
        float n_lo = mx + fast_lg2(1.f + fast_ex2(mn - mx));

        int th = d - u_hi;
        int j1 = min(max(th - 1, 0), T_ - 1);
        int j2 = min(max(th, 0), T_ - 1);
        float w1 = a_hi + sB[j1 * U1_ + uhi_c];
        float w2 = p_hi + sL[j2 * U1_ + uhi_m1];
        float mxh = fmaxf(w1, w2), mnh = fminf(w1, w2);
        float n_hi = mxh + fast_lg2(1.f + fast_ex2(mnh - mxh));

        bool hit = (d == dcap);
        res = (hit && cap_lo) ? n_lo : res;
        res = (hit && cap_hi) ? n_hi : res;
        a_lo = n_lo;
        a_hi = n_hi;
    }

    if (cap_lo || cap_hi) {
        float blank_fin = g_blank[(size_t)b * T_ * U1_ + (size_t)(Tl - 1) * U1_ + Ul];
        out[b] = -(res * LN2 + blank_fin);
    }
}

// ---------------------------------------------------------------------------
extern "C" void kernel_launch(void* const* d_in, const int* in_sizes, int n_in,
                              void* d_out, int out_size)
{
    const float* enc     = (const float*)d_in[0];
    const float* dec     = (const float*)d_in[1];
    const float* We      = (const float*)d_in[2];
    const float* Wd      = (const float*)d_in[3];
    const float* bf      = (const float*)d_in[4];
    const float* Wp      = (const float*)d_in[5];
    const float* bp      = (const float*)d_in[6];
    const int*   targets = (const int*)d_in[7];
    const int*   t_lens  = (const int*)d_in[8];
    const int*   u_lens  = (const int*)d_in[9];
    float* out = (float*)d_out;

    float *pF = nullptr, *pG = nullptr;
    cudaGetSymbolAddress((void**)&pF, g_F);
    cudaGetSymbolAddress((void**)&pG, g_G);

    static bool attr_set = false;
    if (!attr_set) {
        cudaFuncSetAttribute(dp_kernel,
                             cudaFuncAttributeMaxDynamicSharedMemorySize, DP_SMEM);
        cudaFuncSetAttribute(joint_hmma_kernel,
                             cudaFuncAttributeMaxDynamicSharedMemorySize, JSMEM);
        cudaFuncSetAttribute(gemm_hmma_kernel,
                             cudaFuncAttributeMaxDynamicSharedMemorySize, GEMM_SMEM);
        attr_set = true;
    }

    gemm_hmma_kernel<<<dim3(H_ / 64, NB1 + NB2), 256, GEMM_SMEM>>>(
        enc, dec, We, Wd, bf, pF, pG, B_ * T_, B_ * U1_);
    joint_hmma_kernel<<<dim3(T_ / 8, B_), 256, JSMEM>>>(Wp, bp, targets);
    dp_kernel<<<B_, 1024, DP_SMEM>>>(t_lens, u_lens, out);
}

// round 12
// speedup vs baseline: 1.1462x; 1.0980x over previous
#include <cuda_runtime.h>
#include <cuda_bf16.h>
#include <cstdint>

#define B_    8
#define T_    400
#define U_    60
#define U1_   61
#define E_    256
#define H_    512
#define V_    28
#define BLANK_ 27
#define NEGF  (-1e30f)
#define LOG2E 1.4426950408889634f
#define LN2   0.6931471805599453f

// joint smem layout (bytes)
#define GSTR   516
#define DSTR   34
#define SM_G   0
#define SM_F   132096
#define SM_BF  148480
#define SM_D   181248
#define SM_BP  198656
#define JSMEM  198784

// gemm smem
#define GASTR  132
#define GEMM_SMEM (2 * 64 * GASTR * 4)
#define NB1    50
#define NB2    8

// dp smem: 2*T*U1 floats + 128 pad (prefetch overrun)
#define DP_SMEM ((2 * T_ * U1_ + 128) * 4)

// Scratch (no cudaMalloc allowed)
__device__ float g_F[B_*T_*H_];
__device__ float g_G[B_*U1_*H_];
__device__ float g_blank[B_*T_*U1_];
__device__ float g_lab[B_*T_*U1_];

__device__ __forceinline__ float fast_tanh(float x) {
    float y; asm("tanh.approx.f32 %0, %1;" : "=f"(y) : "f"(x)); return y;
}
__device__ __forceinline__ float fast_ex2(float x) {
    float y; asm("ex2.approx.f32 %0, %1;" : "=f"(y) : "f"(x)); return y;
}
__device__ __forceinline__ float fast_lg2(float x) {
    float y; asm("lg2.approx.f32 %0, %1;" : "=f"(y) : "f"(x)); return y;
}
__device__ __forceinline__ uint32_t pack_bf16x2(float lo, float hi) {
    uint32_t r;
    asm("cvt.rn.bf16x2.f32 %0, %1, %2;" : "=r"(r) : "f"(hi), "f"(lo));
    return r;
}
__device__ __forceinline__ void mma_bf16(float& d0, float& d1, float& d2, float& d3,
                                         uint32_t a0, uint32_t a1, uint32_t a2, uint32_t a3,
                                         uint32_t b0, uint32_t b1) {
    asm("mma.sync.aligned.m16n8k16.row.col.f32.bf16.bf16.f32 "
        "{%0,%1,%2,%3}, {%4,%5,%6,%7}, {%8,%9}, {%0,%1,%2,%3};"
        : "+f"(d0), "+f"(d1), "+f"(d2), "+f"(d3)
        : "r"(a0), "r"(a1), "r"(a2), "r"(a3), "r"(b0), "r"(b1));
}

// ---------------------------------------------------------------------------
// Merged bf16 HMMA GEMM, 256 threads (8 warps): blockIdx.y < NB1 -> F; else G.
// Tile 64x64, K=256 smem-resident. Warp w: m-strip (w&3)*16, n-half (w>>2)*32.
// ---------------------------------------------------------------------------
__global__ void __launch_bounds__(256)
gemm_hmma_kernel(const float* __restrict__ A1,
                 const float* __restrict__ A2,
                 const float* __restrict__ B1,
                 const float* __restrict__ B2,
                 const float* __restrict__ bias1,
                 float* __restrict__ C1,
                 float* __restrict__ C2,
                 int M1, int M2)
{
    extern __shared__ uint32_t gsm[];
    uint32_t* sA = gsm;
    uint32_t* sB = gsm + 64 * GASTR;

    const int tid  = threadIdx.x;
    const int wid  = tid >> 5;
    const int lane = tid & 31;
    const int N = H_;

    const float* A; const float* Bm; const float* bias; float* C;
    int M, mb;
    if (blockIdx.y < NB1) {
        A = A1; Bm = B1; bias = bias1; C = C1; M = M1; mb = blockIdx.y * 64;
    } else {
        A = A2; Bm = B2; bias = nullptr; C = C2; M = M2; mb = (blockIdx.y - NB1) * 64;
    }
    const int nb = blockIdx.x * 64;

    for (int i = tid; i < 64 * 64; i += 256) {
        int r  = i >> 6;
        int k4 = i & 63;
        int gm = mb + r;
        float4 v = make_float4(0.f, 0.f, 0.f, 0.f);
        if (gm < M) v = *(const float4*)(A + (size_t)gm * 256 + k4 * 4);
        sA[r * GASTR + k4 * 2]     = pack_bf16x2(v.x, v.y);
        sA[r * GASTR + k4 * 2 + 1] = pack_bf16x2(v.z, v.w);
    }
    for (int i = tid; i < 128 * 16; i += 256) {
        int k2 = i >> 4;
        int n4 = (i & 15) * 4;
        const float* p0 = Bm + (size_t)(2 * k2) * N + nb + n4;
        float4 r0 = *(const float4*)p0;
        float4 r1 = *(const float4*)(p0 + N);
        sB[(n4 + 0) * GASTR + k2] = pack_bf16x2(r0.x, r1.x);
        sB[(n4 + 1) * GASTR + k2] = pack_bf16x2(r0.y, r1.y);
        sB[(n4 + 2) * GASTR + k2] = pack_bf16x2(r0.z, r1.z);
        sB[(n4 + 3) * GASTR + k2] = pack_bf16x2(r0.w, r1.w);
    }
    __syncthreads();

    const int gr = lane >> 2;
    const int c  = lane & 3;
    const int mrow  = (wid & 3) * 16;
    const int nhalf = (wid >> 2) * 4;
    const uint32_t* pa  = sA + (mrow + gr) * GASTR;
    const uint32_t* pa8 = pa + 8 * GASTR;
    const uint32_t* pbn = sB + gr * GASTR + nhalf * 8 * GASTR;

    float d0[4], d1[4], d2[4], d3[4];
    #pragma unroll
    for (int nt = 0; nt < 4; nt++) { d0[nt] = d1[nt] = d2[nt] = d3[nt] = 0.f; }

    #pragma unroll 4
    for (int ch = 0; ch < 16; ch++) {
        int k2b = ch * 8;
        uint32_t a0 = pa[k2b + c];
        uint32_t a1 = pa8[k2b + c];
        uint32_t a2 = pa[k2b + 4 + c];
        uint32_t a3 = pa8[k2b + 4 + c];
        #pragma unroll
        for (int nt = 0; nt < 4; nt++) {
            uint32_t b0 = pbn[nt * 8 * GASTR + k2b + c];
            uint32_t b1 = pbn[nt * 8 * GASTR + k2b + 4 + c];
            mma_bf16(d0[nt], d1[nt], d2[nt], d3[nt], a0, a1, a2, a3, b0, b1);
        }
    }

    int gm0 = mb + mrow + gr;
    int gm1 = gm0 + 8;
    #pragma unroll
    for (int nt = 0; nt < 4; nt++) {
        int gn = nb + (nhalf + nt) * 8 + 2 * c;
        float bb0 = bias ? bias[gn]     : 0.f;
        float bb1 = bias ? bias[gn + 1] : 0.f;
        if (gm0 < M) *(float2*)(C + (size_t)gm0 * N + gn) = make_float2(d0[nt] + bb0, d1[nt] + bb1);
        if (gm1 < M) *(float2*)(C + (size_t)gm1 * N + gn) = make_float2(d2[nt] + bb0, d3[nt] + bb1);
    }
}

// ---------------------------------------------------------------------------
// HMMA joint kernel — exact R9 version (scalar conflict-free B-frag loads).
// ---------------------------------------------------------------------------
__global__ void __launch_bounds__(256)
joint_hmma_kernel(const float* __restrict__ Wp,
                  const float* __restrict__ bp,
                  const int*  __restrict__ targets)
{
    extern __shared__ char smraw[];
    float*    sG  = (float*)(smraw + SM_G);
    float*    sF  = (float*)(smraw + SM_F);
    uint32_t* sBf = (uint32_t*)(smraw + SM_BF);
    float*    sD  = (float*)(smraw + SM_D);
    float*    sBp = (float*)(smraw + SM_BP);

    const int b     = blockIdx.y;
    const int tbase = blockIdx.x * 8;
    const int tid   = threadIdx.x;
    const int wid   = tid >> 5;
    const int lane  = tid & 31;

    const float* Fb = g_F + (size_t)(b * T_ + tbase) * H_;
    const float* Gb = g_G + (size_t)b * U1_ * H_;

    if (tid < V_) sBp[tid] = bp[tid];

    for (int i = tid; i < 64 * (H_ / 4); i += 256) {
        int r = i >> 7;
        int cc = (i & 127) << 2;
        float4 v4 = make_float4(0.f, 0.f, 0.f, 0.f);
        if (r < U1_) v4 = *(const float4*)(Gb + (size_t)r * H_ + cc);
        *(float4*)&sG[r * GSTR + cc] = v4;
    }
    for (int i = tid; i < 8 * (H_ / 4); i += 256) {
        int r = i >> 7;
        int cc = (i & 127) << 2;
        *(float4*)&sF[r * H_ + cc] = *(const float4*)(Fb + (size_t)r * H_ + cc);
    }
    for (int i = tid; i < 32 * 4 * 32; i += 256) {
        int ch = i >> 7;
        int nt = (i >> 5) & 3;
        int l  = i & 31;
        int kA = ch * 16 + 2 * (l & 3);
        int n  = nt * 8 + (l >> 2);
        uint32_t b0 = 0, b1 = 0;
        if (n < V_) {
            b0 = pack_bf16x2(Wp[(size_t)kA * V_ + n],       Wp[(size_t)(kA + 1) * V_ + n]);
            b1 = pack_bf16x2(Wp[(size_t)(kA + 8) * V_ + n], Wp[(size_t)(kA + 9) * V_ + n]);
        }
        sBf[(size_t)i * 2 + 0] = b0;
        sBf[(size_t)i * 2 + 1] = b1;
    }
    __syncthreads();

    const int s    = wid & 3;
    const int tsub = wid >> 2;
    const int u0   = s * 16;
    const int gr    = lane >> 2;
    const int cbase = (lane & 3) * 2;

    const float* gRowA = sG + (u0 + gr) * GSTR;
    const float* gRowB = sG + (u0 + gr + 8) * GSTR;
    float* sDw = sD + wid * (16 * DSTR);

    #pragma unroll 1
    for (int it = 0; it < 4; it++) {
        const int tloc = tsub * 4 + it;
        const float* fRow = sF + tloc * H_;

        float d0[4], d1[4], d2[4], d3[4];
        #pragma unroll
        for (int nt = 0; nt < 4; nt++) { d0[nt] = d1[nt] = d2[nt] = d3[nt] = 0.f; }

        #pragma unroll 2
        for (int ch = 0; ch < 32; ch++) {
            int k = ch * 16 + cbase;
            float2 fA  = *(const float2*)(fRow  + k);
            float2 fB  = *(const float2*)(fRow  + k + 8);
            float2 gAa = *(const float2*)(gRowA + k);
            float2 gBa = *(const float2*)(gRowA + k + 8);
            float2 gAb = *(const float2*)(gRowB + k);
            float2 gBb = *(const float2*)(gRowB + k + 8);
            uint32_t a0 = pack_bf16x2(fast_tanh(fA.x + gAa.x), fast_tanh(fA.y + gAa.y));
            uint32_t a1 = pack_bf16x2(fast_tanh(fA.x + gAb.x), fast_tanh(fA.y + gAb.y));
            uint32_t a2 = pack_bf16x2(fast_tanh(fB.x + gBa.x), fast_tanh(fB.y + gBa.y));
            uint32_t a3 = pack_bf16x2(fast_tanh(fB.x + gBb.x), fast_tanh(fB.y + gBb.y));
            const uint32_t* bf = sBf + (size_t)(ch * 4) * 64 + lane * 2;
            #pragma unroll
            for (int nt = 0; nt < 4; nt++) {
                uint32_t bb0 = bf[nt * 64 + 0];
                uint32_t bb1 = bf[nt * 64 + 1];
                mma_bf16(d0[nt], d1[nt], d2[nt], d3[nt], a0, a1, a2, a3, bb0, bb1);
            }
        }

        #pragma unroll
        for (int nt = 0; nt < 4; nt++) {
            int cc = nt * 8 + cbase;
            *(float2*)&sDw[gr * DSTR + cc]       = make_float2(d0[nt], d1[nt]);
            *(float2*)&sDw[(gr + 8) * DSTR + cc] = make_float2(d2[nt], d3[nt]);
        }
        __syncwarp();

        if (lane < 16) {
            int u = u0 + lane;
            if (u < U1_) {
                int t = tbase + tloc;
                float logits[V_];
                float m = -1e30f;
                #pragma unroll
                for (int v = 0; v < V_; v++) {
                    logits[v] = sDw[lane * DSTR + v] + sBp[v];
                    m = fmaxf(m, logits[v]);
                }
                float ssum = 0.f;
                #pragma unroll
                for (int v = 0; v < V_; v++) ssum += fast_ex2((logits[v] - m) * LOG2E);
                float lse = m + fast_lg2(ssum) * LN2;

                int tgt = (u < U_) ? targets[b * U_ + u] : 0;
                float lv = logits[0];
                #pragma unroll
                for (int v = 1; v < V_; v++)
                    if (v == tgt) lv = logits[v];

                size_t idx = (size_t)(b * T_ + t) * U1_ + u;
                g_blank[idx] = logits[BLANK_] - lse;
                if (u < U_) g_lab[idx] = lv - lse;
            }
        }
        __syncwarp();
    }
}

// ---------------------------------------------------------------------------
// Forward DP: phase-split wavefront, 2 shfls/step, terminates at dcap,
// stages only the rows the wavefront touches.
// ---------------------------------------------------------------------------
__global__ void dp_kernel(const int* __restrict__ t_lens,
                          const int* __restrict__ u_lens,
                          float* __restrict__ out)
{
    extern __shared__ float sm[];
    float* sB = sm;
    float* sL = sm + T_ * U1_;

    int b   = blockIdx.x;
    int tid = threadIdx.x;

    const int Tl = t_lens[b], Ul = u_lens[b];
    const int dcap = (Tl - 1) + Ul;          // in [229, 459]

    const float4* srcB = (const float4*)(g_blank + (size_t)b * T_ * U1_);
    const float4* srcL = (const float4*)(g_lab   + (size_t)b * T_ * U1_);
    const int nrows = min(T_, dcap + 2);
    const int n4 = (nrows * U1_ + 3) / 4;
    for (int i = tid; i < n4; i += 1024) {
        float4 vb = srcB[i];
        float4 vl = srcL[i];
        vb.x *= LOG2E; vb.y *= LOG2E; vb.z *= LOG2E; vb.w *= LOG2E;
        vl.x *= LOG2E; vl.y *= LOG2E; vl.z *= LOG2E; vl.w *= LOG2E;
        ((float4*)sB)[i] = vb;
        ((float4*)sL)[i] = vl;
    }
    __syncthreads();
    if (tid >= 32) return;

    const int lane = tid;
    const bool cap_lo = (Ul < 32) && (lane == Ul);
    const bool cap_hi = (Ul >= 32) && (lane == Ul - 32);
    const int srcl = (lane + 31) & 31;

    const int u_lo = lane;
    const int u_hi = lane + 32;
    const int ulo_m1 = max(u_lo - 1, 0);
    const int uhi_c  = min(u_hi, U1_ - 1);
    const int uhi_m1 = min(u_hi - 1, U1_ - 1);

    float a_lo = (lane == 0) ? 0.f : NEGF;
    float a_hi = NEGF;
    float res  = 0.f;

    for (int d = 1; d <= 63; d++) {
        float p_lo = __shfl_up_sync(0xffffffffu, a_lo, 1);
        p_lo = (lane == 0) ? NEGF : p_lo;
        float yh   = (lane == 31) ? a_lo : a_hi;
        float p_hi = __shfl_sync(0xffffffffu, yh, srcl);

        int t  = d - u_lo;
        int i1 = min(max(t - 1, 0), T_ - 1);
        int i2 = min(max(t, 0), T_ - 1);
        float v1 = a_lo + sB[i1 * U1_ + u_lo];
        float v2 = p_lo + sL[i2 * U1_ + ulo_m1];
        float mx = fmaxf(v1, v2), mn = fminf(v1, v2);
        a_lo = mx + fast_lg2(1.f + fast_ex2(mn - mx));

        int th = d - u_hi;
        int j1 = min(max(th - 1, 0), T_ - 1);
        int j2 = min(max(th, 0), T_ - 1);
        float w1 = a_hi + sB[j1 * U1_ + uhi_c];
        float w2 = p_hi + sL[j2 * U1_ + uhi_m1];
        float mxh = fmaxf(w1, w2), mnh = fminf(w1, w2);
        a_hi = mxh + fast_lg2(1.f + fast_ex2(mnh - mxh));
    }

    {
        const int d2end = min(399, dcap);
        int ob_lo = (63 - u_lo) * U1_ + u_lo;
        int ol_lo = (64 - u_lo) * U1_ + ulo_m1;
        int ob_hi = (63 - u_hi) * U1_ + uhi_c;
        int ol_hi = (64 - u_hi) * U1_ + uhi_m1;

        float Blo = sB[ob_lo], Llo = sL[ol_lo];
        float Bhi = sB[ob_hi], Lhi = sL[ol_hi];

        #pragma unroll 2
        for (int d = 64; d <= d2end; d++) {
            ob_lo += U1_; ol_lo += U1_; ob_hi += U1_; ol_hi += U1_;
            float nBlo = sB[ob_lo];
            float nLlo = sL[ol_lo];
            float nBhi = sB[ob_hi];
            float nLhi = sL[ol_hi];

            float p_lo = __shfl_up_sync(0xffffffffu, a_lo, 1);
            p_lo = (lane == 0) ? NEGF : p_lo;
            float yh   = (lane == 31) ? a_lo : a_hi;
            float p_hi = __shfl_sync(0xffffffffu, yh, srcl);

            float v1 = a_lo + Blo;
            float v2 = p_lo + Llo;
            float mx = fmaxf(v1, v2), mn = fminf(v1, v2);
            float n_lo = mx + fast_lg2(1.f + fast_ex2(mn - mx));

            float w1 = a_hi + Bhi;
            float w2 = p_hi + Lhi;
            float mxh = fmaxf(w1, w2), mnh = fminf(w1, w2);
            float n_hi = mxh + fast_lg2(1.f + fast_ex2(mnh - mxh));

            bool hit = (d == dcap);
            res = (hit && cap_lo) ? n_lo : res;
            res = (hit && cap_hi) ? n_hi : res;
            a_lo = n_lo;
            a_hi = n_hi;
            Blo = nBlo; Llo = nLlo; Bhi = nBhi; Lhi = nLhi;
        }
    }

    for (int d = 400; d <= dcap; d++) {
        float p_lo = __shfl_up_sync(0xffffffffu, a_lo, 1);
        p_lo = (lane == 0) ? NEGF : p_lo;
        float yh   = (lane == 31) ? a_lo : a_hi;
        float p_hi = __shfl_sync(0xffffffffu, yh, srcl);

        int t  = d - u_lo;
        int i1 = min(max(t - 1, 0), T_ - 1);
        int i2 = min(max(t, 0), T_ - 1);
        float v1 = a_lo + sB[i1 * U1_ + u_lo];
        float v2 = p_lo + sL[i2 * U1_ + ulo_m1];
        float mx = fmaxf(v1, v2), mn = fminf(v1, v2);
        float n_lo = mx + fast_lg2(1.f + fast_ex2(mn - mx));

        int th = d - u_hi;
        int j1 = min(max(th - 1, 0), T_ - 1);
        int j2 = min(max(th, 0), T_ - 1);
        float w1 = a_hi + sB[j1 * U1_ + uhi_c];
        float w2 = p_hi + sL[j2 * U1_ + uhi_m1];
        float mxh = fmaxf(w1, w2), mnh = fminf(w1, w2);
        float n_hi = mxh + fast_lg2(1.f + fast_ex2(mnh - mxh));

        bool hit = (d == dcap);
        res = (hit && cap_lo) ? n_lo : res;
        res = (hit && cap_hi) ? n_hi : res;
        a_lo = n_lo;
        a_hi = n_hi;
    }

    if (cap_lo || cap_hi) {
        float blank_fin = g_blank[(size_t)b * T_ * U1_ + (size_t)(Tl - 1) * U1_ + Ul];
        out[b] = -(res * LN2 + blank_fin);
    }
}

// ---------------------------------------------------------------------------
extern "C" void kernel_launch(void* const* d_in, const int* in_sizes, int n_in,
                              void* d_out, int out_size)
{
    const float* enc     = (const float*)d_in[0];
    const float* dec     = (const float*)d_in[1];
    const float* We      = (const float*)d_in[2];
    const float* Wd      = (const float*)d_in[3];
    const float* bf      = (const float*)d_in[4];
    const float* Wp      = (const float*)d_in[5];
    const float* bp      = (const float*)d_in[6];
    const int*   targets = (const int*)d_in[7];
    const int*   t_lens  = (const int*)d_in[8];
    const int*   u_lens  = (const int*)d_in[9];
    float* out = (float*)d_out;

    float *pF = nullptr, *pG = nullptr;
    cudaGetSymbolAddress((void**)&pF, g_F);
    cudaGetSymbolAddress((void**)&pG, g_G);

    static bool attr_set = false;
    if (!attr_set) {
        cudaFuncSetAttribute(dp_kernel,
                             cudaFuncAttributeMaxDynamicSharedMemorySize, DP_SMEM);
        cudaFuncSetAttribute(joint_hmma_kernel,
                             cudaFuncAttributeMaxDynamicSharedMemorySize, JSMEM);
        cudaFuncSetAttribute(gemm_hmma_kernel,
                             cudaFuncAttributeMaxDynamicSharedMemorySize, GEMM_SMEM);
        attr_set = true;
    }

    gemm_hmma_kernel<<<dim3(H_ / 64, NB1 + NB2), 256, GEMM_SMEM>>>(
        enc, dec, We, Wd, bf, pF, pG, B_ * T_, B_ * U1_);
    joint_hmma_kernel<<<dim3(T_ / 8, B_), 256, JSMEM>>>(Wp, bp, targets);
    dp_kernel<<<B_, 1024, DP_SMEM>>>(t_lens, u_lens, out);
}

// round 13
// speedup vs baseline: 1.1652x; 1.0166x over previous
#include <cuda_runtime.h>
#include <cuda_bf16.h>
#include <cstdint>

#define B_    8
#define T_    400
#define U_    60
#define U1_   61
#define E_    256
#define H_    512
#define V_    28
#define BLANK_ 27
#define NEGF  (-1e30f)
#define LOG2E 1.4426950408889634f
#define LN2   0.6931471805599453f

// joint smem layout (bytes) — 16-warp version
#define GSTR   516
#define DSTR   34
#define SM_G   0                              // 64*516*4  = 132096
#define SM_F   132096                         // 8*512*4   = 16384
#define SM_BF  148480                         // 32*4*32*8 = 32768
#define SM_D   181248                         // 16*16*34*4= 34816
#define SM_BP  216064                         // 128
#define JSMEM  216192

// gemm smem
#define GASTR  132
#define GEMM_SMEM (2 * 64 * GASTR * 4)
#define NB1    50
#define NB2    8

// dp smem: 2*T*U1 floats + 128 pad (prefetch overrun)
#define DP_SMEM ((2 * T_ * U1_ + 128) * 4)

// Scratch (no cudaMalloc allowed)
__device__ float g_F[B_*T_*H_];
__device__ float g_G[B_*U1_*H_];
__device__ float g_blank[B_*T_*U1_];
__device__ float g_lab[B_*T_*U1_];

__device__ __forceinline__ float fast_tanh(float x) {
    float y; asm("tanh.approx.f32 %0, %1;" : "=f"(y) : "f"(x)); return y;
}
__device__ __forceinline__ float fast_ex2(float x) {
    float y; asm("ex2.approx.f32 %0, %1;" : "=f"(y) : "f"(x)); return y;
}
__device__ __forceinline__ float fast_lg2(float x) {
    float y; asm("lg2.approx.f32 %0, %1;" : "=f"(y) : "f"(x)); return y;
}
__device__ __forceinline__ uint32_t pack_bf16x2(float lo, float hi) {
    uint32_t r;
    asm("cvt.rn.bf16x2.f32 %0, %1, %2;" : "=r"(r) : "f"(hi), "f"(lo));
    return r;
}
__device__ __forceinline__ void mma_bf16(float& d0, float& d1, float& d2, float& d3,
                                         uint32_t a0, uint32_t a1, uint32_t a2, uint32_t a3,
                                         uint32_t b0, uint32_t b1) {
    asm("mma.sync.aligned.m16n8k16.row.col.f32.bf16.bf16.f32 "
        "{%0,%1,%2,%3}, {%4,%5,%6,%7}, {%8,%9}, {%0,%1,%2,%3};"
        : "+f"(d0), "+f"(d1), "+f"(d2), "+f"(d3)
        : "r"(a0), "r"(a1), "r"(a2), "r"(a3), "r"(b0), "r"(b1));
}

// ---------------------------------------------------------------------------
// Merged bf16 HMMA GEMM, 256 threads (8 warps): blockIdx.y < NB1 -> F; else G.
// ---------------------------------------------------------------------------
__global__ void __launch_bounds__(256)
gemm_hmma_kernel(const float* __restrict__ A1,
                 const float* __restrict__ A2,
                 const float* __restrict__ B1,
                 const float* __restrict__ B2,
                 const float* __restrict__ bias1,
                 float* __restrict__ C1,
                 float* __restrict__ C2,
                 int M1, int M2)
{
    extern __shared__ uint32_t gsm[];
    uint32_t* sA = gsm;
    uint32_t* sB = gsm + 64 * GASTR;

    const int tid  = threadIdx.x;
    const int wid  = tid >> 5;
    const int lane = tid & 31;
    const int N = H_;

    const float* A; const float* Bm; const float* bias; float* C;
    int M, mb;
    if (blockIdx.y < NB1) {
        A = A1; Bm = B1; bias = bias1; C = C1; M = M1; mb = blockIdx.y * 64;
    } else {
        A = A2; Bm = B2; bias = nullptr; C = C2; M = M2; mb = (blockIdx.y - NB1) * 64;
    }
    const int nb = blockIdx.x * 64;

    for (int i = tid; i < 64 * 64; i += 256) {
        int r  = i >> 6;
        int k4 = i & 63;
        int gm = mb + r;
        float4 v = make_float4(0.f, 0.f, 0.f, 0.f);
        if (gm < M) v = *(const float4*)(A + (size_t)gm * 256 + k4 * 4);
        sA[r * GASTR + k4 * 2]     = pack_bf16x2(v.x, v.y);
        sA[r * GASTR + k4 * 2 + 1] = pack_bf16x2(v.z, v.w);
    }
    for (int i = tid; i < 128 * 16; i += 256) {
        int k2 = i >> 4;
        int n4 = (i & 15) * 4;
        const float* p0 = Bm + (size_t)(2 * k2) * N + nb + n4;
        float4 r0 = *(const float4*)p0;
        float4 r1 = *(const float4*)(p0 + N);
        sB[(n4 + 0) * GASTR + k2] = pack_bf16x2(r0.x, r1.x);
        sB[(n4 + 1) * GASTR + k2] = pack_bf16x2(r0.y, r1.y);
        sB[(n4 + 2) * GASTR + k2] = pack_bf16x2(r0.z, r1.z);
        sB[(n4 + 3) * GASTR + k2] = pack_bf16x2(r0.w, r1.w);
    }
    __syncthreads();

    const int gr = lane >> 2;
    const int c  = lane & 3;
    const int mrow  = (wid & 3) * 16;
    const int nhalf = (wid >> 2) * 4;
    const uint32_t* pa  = sA + (mrow + gr) * GASTR;
    const uint32_t* pa8 = pa + 8 * GASTR;
    const uint32_t* pbn = sB + gr * GASTR + nhalf * 8 * GASTR;

    float d0[4], d1[4], d2[4], d3[4];
    #pragma unroll
    for (int nt = 0; nt < 4; nt++) { d0[nt] = d1[nt] = d2[nt] = d3[nt] = 0.f; }

    #pragma unroll 4
    for (int ch = 0; ch < 16; ch++) {
        int k2b = ch * 8;
        uint32_t a0 = pa[k2b + c];
        uint32_t a1 = pa8[k2b + c];
        uint32_t a2 = pa[k2b + 4 + c];
        uint32_t a3 = pa8[k2b + 4 + c];
        #pragma unroll
        for (int nt = 0; nt < 4; nt++) {
            uint32_t b0 = pbn[nt * 8 * GASTR + k2b + c];
            uint32_t b1 = pbn[nt * 8 * GASTR + k2b + 4 + c];
            mma_bf16(d0[nt], d1[nt], d2[nt], d3[nt], a0, a1, a2, a3, b0, b1);
        }
    }

    int gm0 = mb + mrow + gr;
    int gm1 = gm0 + 8;
    #pragma unroll
    for (int nt = 0; nt < 4; nt++) {
        int gn = nb + (nhalf + nt) * 8 + 2 * c;
        float bb0 = bias ? bias[gn]     : 0.f;
        float bb1 = bias ? bias[gn + 1] : 0.f;
        if (gm0 < M) *(float2*)(C + (size_t)gm0 * N + gn) = make_float2(d0[nt] + bb0, d1[nt] + bb1);
        if (gm1 < M) *(float2*)(C + (size_t)gm1 * N + gn) = make_float2(d2[nt] + bb0, d3[nt] + bb1);
    }
}

// ---------------------------------------------------------------------------
// HMMA joint kernel — 512 threads / 16 warps (2x occupancy vs R12).
// Warp w: u-strip s = w&3 (u0=16s), tsub = w>>2 (0..3); loops 2 t values
// (tloc = tsub*2 + it). Same fragment layout / arithmetic as R9/R12.
// ---------------------------------------------------------------------------
__global__ void __launch_bounds__(512)
joint_hmma_kernel(const float* __restrict__ Wp,
                  const float* __restrict__ bp,
                  const int*  __restrict__ targets)
{
    extern __shared__ char smraw[];
    float*    sG  = (float*)(smraw + SM_G);
    float*    sF  = (float*)(smraw + SM_F);
    uint32_t* sBf = (uint32_t*)(smraw + SM_BF);
    float*    sD  = (float*)(smraw + SM_D);
    float*    sBp = (float*)(smraw + SM_BP);

    const int b     = blockIdx.y;
    const int tbase = blockIdx.x * 8;
    const int tid   = threadIdx.x;
    const int wid   = tid >> 5;
    const int lane  = tid & 31;

    const float* Fb = g_F + (size_t)(b * T_ + tbase) * H_;
    const float* Gb = g_G + (size_t)b * U1_ * H_;

    if (tid < V_) sBp[tid] = bp[tid];

    for (int i = tid; i < 64 * (H_ / 4); i += 512) {
        int r = i >> 7;
        int cc = (i & 127) << 2;
        float4 v4 = make_float4(0.f, 0.f, 0.f, 0.f);
        if (r < U1_) v4 = *(const float4*)(Gb + (size_t)r * H_ + cc);
        *(float4*)&sG[r * GSTR + cc] = v4;
    }
    for (int i = tid; i < 8 * (H_ / 4); i += 512) {
        int r = i >> 7;
        int cc = (i & 127) << 2;
        *(float4*)&sF[r * H_ + cc] = *(const float4*)(Fb + (size_t)r * H_ + cc);
    }
    for (int i = tid; i < 32 * 4 * 32; i += 512) {
        int ch = i >> 7;
        int nt = (i >> 5) & 3;
        int l  = i & 31;
        int kA = ch * 16 + 2 * (l & 3);
        int n  = nt * 8 + (l >> 2);
        uint32_t b0 = 0, b1 = 0;
        if (n < V_) {
            b0 = pack_bf16x2(Wp[(size_t)kA * V_ + n],       Wp[(size_t)(kA + 1) * V_ + n]);
            b1 = pack_bf16x2(Wp[(size_t)(kA + 8) * V_ + n], Wp[(size_t)(kA + 9) * V_ + n]);
        }
        sBf[(size_t)i * 2 + 0] = b0;
        sBf[(size_t)i * 2 + 1] = b1;
    }
    __syncthreads();

    const int s    = wid & 3;
    const int tsub = wid >> 2;            // 0..3
    const int u0   = s * 16;
    const int gr    = lane >> 2;
    const int cbase = (lane & 3) * 2;

    const float* gRowA = sG + (u0 + gr) * GSTR;
    const float* gRowB = sG + (u0 + gr + 8) * GSTR;
    float* sDw = sD + wid * (16 * DSTR);

    #pragma unroll 1
    for (int it = 0; it < 2; it++) {
        const int tloc = tsub * 2 + it;
        const float* fRow = sF + tloc * H_;

        float d0[4], d1[4], d2[4], d3[4];
        #pragma unroll
        for (int nt = 0; nt < 4; nt++) { d0[nt] = d1[nt] = d2[nt] = d3[nt] = 0.f; }

        #pragma unroll 2
        for (int ch = 0; ch < 32; ch++) {
            int k = ch * 16 + cbase;
            float2 fA  = *(const float2*)(fRow  + k);
            float2 fB  = *(const float2*)(fRow  + k + 8);
            float2 gAa = *(const float2*)(gRowA + k);
            float2 gBa = *(const float2*)(gRowA + k + 8);
            float2 gAb = *(const float2*)(gRowB + k);
            float2 gBb = *(const float2*)(gRowB + k + 8);
            uint32_t a0 = pack_bf16x2(fast_tanh(fA.x + gAa.x), fast_tanh(fA.y + gAa.y));
            uint32_t a1 = pack_bf16x2(fast_tanh(fA.x + gAb.x), fast_tanh(fA.y + gAb.y));
            uint32_t a2 = pack_bf16x2(fast_tanh(fB.x + gBa.x), fast_tanh(fB.y + gBa.y));
            uint32_t a3 = pack_bf16x2(fast_tanh(fB.x + gBb.x), fast_tanh(fB.y + gBb.y));
            const uint32_t* bf = sBf + (size_t)(ch * 4) * 64 + lane * 2;
            #pragma unroll
            for (int nt = 0; nt < 4; nt++) {
                uint32_t bb0 = bf[nt * 64 + 0];
                uint32_t bb1 = bf[nt * 64 + 1];
                mma_bf16(d0[nt], d1[nt], d2[nt], d3[nt], a0, a1, a2, a3, bb0, bb1);
            }
        }

        #pragma unroll
        for (int nt = 0; nt < 4; nt++) {
            int cc = nt * 8 + cbase;
            *(float2*)&sDw[gr * DSTR + cc]       = make_float2(d0[nt], d1[nt]);
            *(float2*)&sDw[(gr + 8) * DSTR + cc] = make_float2(d2[nt], d3[nt]);
        }
        __syncwarp();

        if (lane < 16) {
            int u = u0 + lane;
            if (u < U1_) {
                int t = tbase + tloc;
                float logits[V_];
                float m = -1e30f;
                #pragma unroll
                for (int v = 0; v < V_; v++) {
                    logits[v] = sDw[lane * DSTR + v] + sBp[v];
                    m = fmaxf(m, logits[v]);
                }
                float ssum = 0.f;
                #pragma unroll
                for (int v = 0; v < V_; v++) ssum += fast_ex2((logits[v] - m) * LOG2E);
                float lse = m + fast_lg2(ssum) * LN2;

                int tgt = (u < U_) ? targets[b * U_ + u] : 0;
                float lv = logits[0];
                #pragma unroll
                for (int v = 1; v < V_; v++)
                    if (v == tgt) lv = logits[v];

                size_t idx = (size_t)(b * T_ + t) * U1_ + u;
                g_blank[idx] = logits[BLANK_] - lse;
                if (u < U_) g_lab[idx] = lv - lse;
            }
        }
        __syncwarp();
    }
}

// ---------------------------------------------------------------------------
// Forward DP (R12: phase-split, 2 shfls/step, dcap-bounded).
// ---------------------------------------------------------------------------
__global__ void dp_kernel(const int* __restrict__ t_lens,
                          const int* __restrict__ u_lens,
                          float* __restrict__ out)
{
    extern __shared__ float sm[];
    float* sB = sm;
    float* sL = sm + T_ * U1_;

    int b   = blockIdx.x;
    int tid = threadIdx.x;

    const int Tl = t_lens[b], Ul = u_lens[b];
    const int dcap = (Tl - 1) + Ul;

    const float4* srcB = (const float4*)(g_blank + (size_t)b * T_ * U1_);
    const float4* srcL = (const float4*)(g_lab   + (size_t)b * T_ * U1_);
    const int nrows = min(T_, dcap + 2);
    const int n4 = (nrows * U1_ + 3) / 4;
    for (int i = tid; i < n4; i += 1024) {
        float4 vb = srcB[i];
        float4 vl = srcL[i];
        vb.x *= LOG2E; vb.y *= LOG2E; vb.z *= LOG2E; vb.w *= LOG2E;
        vl.x *= LOG2E; vl.y *= LOG2E; vl.z *= LOG2E; vl.w *= LOG2E;
        ((float4*)sB)[i] = vb;
        ((float4*)sL)[i] = vl;
    }
    __syncthreads();
    if (tid >= 32) return;

    const int lane = tid;
    const bool cap_lo = (Ul < 32) && (lane == Ul);
    const bool cap_hi = (Ul >= 32) && (lane == Ul - 32);
    const int srcl = (lane + 31) & 31;

    const int u_lo = lane;
    const int u_hi = lane + 32;
    const int ulo_m1 = max(u_lo - 1, 0);
    const int uhi_c  = min(u_hi, U1_ - 1);
    const int uhi_m1 = min(u_hi - 1, U1_ - 1);

    float a_lo = (lane == 0) ? 0.f : NEGF;
    float a_hi = NEGF;
    float res  = 0.f;

    for (int d = 1; d <= 63; d++) {
        float p_lo = __shfl_up_sync(0xffffffffu, a_lo, 1);
        p_lo = (lane == 0) ? NEGF : p_lo;
        float yh   = (lane == 31) ? a_lo : a_hi;
        float p_hi = __shfl_sync(0xffffffffu, yh, srcl);

        int t  = d - u_lo;
        int i1 = min(max(t - 1, 0), T_ - 1);
        int i2 = min(max(t, 0), T_ - 1);
        float v1 = a_lo + sB[i1 * U1_ + u_lo];
        float v2 = p_lo + sL[i2 * U1_ + ulo_m1];
        float mx = fmaxf(v1, v2), mn = fminf(v1, v2);
        a_lo = mx + fast_lg2(1.f + fast_ex2(mn - mx));

        int th = d - u_hi;
        int j1 = min(max(th - 1, 0), T_ - 1);
        int j2 = min(max(th, 0), T_ - 1);
        float w1 = a_hi + sB[j1 * U1_ + uhi_c];
        float w2 = p_hi + sL[j2 * U1_ + uhi_m1];
        float mxh = fmaxf(w1, w2), mnh = fminf(w1, w2);
        a_hi = mxh + fast_lg2(1.f + fast_ex2(mnh - mxh));
    }

    {
        const int d2end = min(399, dcap);
        int ob_lo = (63 - u_lo) * U1_ + u_lo;
        int ol_lo = (64 - u_lo) * U1_ + ulo_m1;
        int ob_hi = (63 - u_hi) * U1_ + uhi_c;
        int ol_hi = (64 - u_hi) * U1_ + uhi_m1;

        float Blo = sB[ob_lo], Llo = sL[ol_lo];
        float Bhi = sB[ob_hi], Lhi = sL[ol_hi];

        #pragma unroll 2
        for (int d = 64; d <= d2end; d++) {
            ob_lo += U1_; ol_lo += U1_; ob_hi += U1_; ol_hi += U1_;
            float nBlo = sB[ob_lo];
            float nLlo = sL[ol_lo];
            float nBhi = sB[ob_hi];
            float nLhi = sL[ol_hi];

            float p_lo = __shfl_up_sync(0xffffffffu, a_lo, 1);
            p_lo = (lane == 0) ? NEGF : p_lo;
            float yh   = (lane == 31) ? a_lo : a_hi;
            float p_hi = __shfl_sync(0xffffffffu, yh, srcl);

            float v1 = a_lo + Blo;
            float v2 = p_lo + Llo;
            float mx = fmaxf(v1, v2), mn = fminf(v1, v2);
            float n_lo = mx + fast_lg2(1.f + fast_ex2(mn - mx));

            float w1 = a_hi + Bhi;
            float w2 = p_hi + Lhi;
            float mxh = fmaxf(w1, w2), mnh = fminf(w1, w2);
            float n_hi = mxh + fast_lg2(1.f + fast_ex2(mnh - mxh));

            bool hit = (d == dcap);
            res = (hit && cap_lo) ? n_lo : res;
            res = (hit && cap_hi) ? n_hi : res;
            a_lo = n_lo;
            a_hi = n_hi;
            Blo = nBlo; Llo = nLlo; Bhi = nBhi; Lhi = nLhi;
        }
    }

    for (int d = 400; d <= dcap; d++) {
        float p_lo = __shfl_up_sync(0xffffffffu, a_lo, 1);
        p_lo = (lane == 0) ? NEGF : p_lo;
        float yh   = (lane == 31) ? a_lo : a_hi;
        float p_hi = __shfl_sync(0xffffffffu, yh, srcl);

        int t  = d - u_lo;
        int i1 = min(max(t - 1, 0), T_ - 1);
        int i2 = min(max(t, 0), T_ - 1);
        float v1 = a_lo + sB[i1 * U1_ + u_lo];
        float v2 = p_lo + sL[i2 * U1_ + ulo_m1];
        float mx = fmaxf(v1, v2), mn = fminf(v1, v2);
        float n_lo = mx + fast_lg2(1.f + fast_ex2(mn - mx));

        int th = d - u_hi;
        int j1 = min(max(th - 1, 0), T_ - 1);
        int j2 = min(max(th, 0), T_ - 1);
        float w1 = a_hi + sB[j1 * U1_ + uhi_c];
        float w2 = p_hi + sL[j2 * U1_ + uhi_m1];
        float mxh = fmaxf(w1, w2), mnh = fminf(w1, w2);
        float n_hi = mxh + fast_lg2(1.f + fast_ex2(mnh - mxh));

        bool hit = (d == dcap);
        res = (hit && cap_lo) ? n_lo : res;
        res = (hit && cap_hi) ? n_hi : res;
        a_lo = n_lo;
        a_hi = n_hi;
    }

    if (cap_lo || cap_hi) {
        float blank_fin = g_blank[(size_t)b * T_ * U1_ + (size_t)(Tl - 1) * U1_ + Ul];
        out[b] = -(res * LN2 + blank_fin);
    }
}

// ---------------------------------------------------------------------------
extern "C" void kernel_launch(void* const* d_in, const int* in_sizes, int n_in,
                              void* d_out, int out_size)
{
    const float* enc     = (const float*)d_in[0];
    const float* dec     = (const float*)d_in[1];
    const float* We      = (const float*)d_in[2];
    const float* Wd      = (const float*)d_in[3];
    const float* bf      = (const float*)d_in[4];
    const float* Wp      = (const float*)d_in[5];
    const float* bp      = (const float*)d_in[6];
    const int*   targets = (const int*)d_in[7];
    const int*   t_lens  = (const int*)d_in[8];
    const int*   u_lens  = (const int*)d_in[9];
    float* out = (float*)d_out;

    float *pF = nullptr, *pG = nullptr;
    cudaGetSymbolAddress((void**)&pF, g_F);
    cudaGetSymbolAddress((void**)&pG, g_G);

    static bool attr_set = false;
    if (!attr_set) {
        cudaFuncSetAttribute(dp_kernel,
                             cudaFuncAttributeMaxDynamicSharedMemorySize, DP_SMEM);
        cudaFuncSetAttribute(joint_hmma_kernel,
                             cudaFuncAttributeMaxDynamicSharedMemorySize, JSMEM);
        cudaFuncSetAttribute(gemm_hmma_kernel,
                             cudaFuncAttributeMaxDynamicSharedMemorySize, GEMM_SMEM);
        attr_set = true;
    }

    gemm_hmma_kernel<<<dim3(H_ / 64, NB1 + NB2), 256, GEMM_SMEM>>>(
        enc, dec, We, Wd, bf, pF, pG, B_ * T_, B_ * U1_);
    joint_hmma_kernel<<<dim3(T_ / 8, B_), 512, JSMEM>>>(Wp, bp, targets);
    dp_kernel<<<B_, 1024, DP_SMEM>>>(t_lens, u_lens, out);
}

// round 14
// speedup vs baseline: 1.3065x; 1.1213x over previous
#include <cuda_runtime.h>
#include <cuda_bf16.h>
#include <cstdint>

#define B_    8
#define T_    400
#define U_    60
#define U1_   61
#define E_    256
#define H_    512
#define V_    28
#define BLANK_ 27
#define NEGF  (-1e30f)
#define LOG2E 1.4426950408889634f
#define LN2   0.6931471805599453f

// joint smem layout (bytes) — 16-warp version
#define GSTR   516
#define DSTR   34
#define SM_G   0                              // 64*516*4  = 132096
#define SM_F   132096                         // 8*512*4   = 16384
#define SM_BF  148480                         // 32*4*32*8 = 32768
#define SM_D   181248                         // 16*16*34*4= 34816
#define SM_BP  216064                         // 128
#define JSMEM  216192

// joint tiling: 50 t-tiles of 8, grid.x=17, each block does <=3 tiles
#define JTILES 50
#define JGX    17

// gemm smem
#define GASTR  132
#define GEMM_SMEM (2 * 64 * GASTR * 4)
#define NB1    50
#define NB2    8

// dp smem: 2*T*U1 floats + 128 pad (prefetch overrun)
#define DP_SMEM ((2 * T_ * U1_ + 128) * 4)

// Scratch (no cudaMalloc allowed)
__device__ float g_F[B_*T_*H_];
__device__ float g_G[B_*U1_*H_];
__device__ float g_blank[B_*T_*U1_];
__device__ float g_lab[B_*T_*U1_];

__device__ __forceinline__ float fast_tanh(float x) {
    float y; asm("tanh.approx.f32 %0, %1;" : "=f"(y) : "f"(x)); return y;
}
__device__ __forceinline__ float fast_ex2(float x) {
    float y; asm("ex2.approx.f32 %0, %1;" : "=f"(y) : "f"(x)); return y;
}
__device__ __forceinline__ float fast_lg2(float x) {
    float y; asm("lg2.approx.f32 %0, %1;" : "=f"(y) : "f"(x)); return y;
}
__device__ __forceinline__ uint32_t pack_bf16x2(float lo, float hi) {
    uint32_t r;
    asm("cvt.rn.bf16x2.f32 %0, %1, %2;" : "=r"(r) : "f"(hi), "f"(lo));
    return r;
}
__device__ __forceinline__ void mma_bf16(float& d0, float& d1, float& d2, float& d3,
                                         uint32_t a0, uint32_t a1, uint32_t a2, uint32_t a3,
                                         uint32_t b0, uint32_t b1) {
    asm("mma.sync.aligned.m16n8k16.row.col.f32.bf16.bf16.f32 "
        "{%0,%1,%2,%3}, {%4,%5,%6,%7}, {%8,%9}, {%0,%1,%2,%3};"
        : "+f"(d0), "+f"(d1), "+f"(d2), "+f"(d3)
        : "r"(a0), "r"(a1), "r"(a2), "r"(a3), "r"(b0), "r"(b1));
}

// ---------------------------------------------------------------------------
// Merged bf16 HMMA GEMM, 512 threads (16 warps): blockIdx.y < NB1 -> F; else G.
// Tile 64x64. Warp w: m-strip (w&3)*16, n-quarter (w>>2) -> 2 n-tiles.
// ---------------------------------------------------------------------------
__global__ void __launch_bounds__(512)
gemm_hmma_kernel(const float* __restrict__ A1,
                 const float* __restrict__ A2,
                 const float* __restrict__ B1,
                 const float* __restrict__ B2,
                 const float* __restrict__ bias1,
                 float* __restrict__ C1,
                 float* __restrict__ C2,
                 int M1, int M2)
{
    extern __shared__ uint32_t gsm[];
    uint32_t* sA = gsm;
    uint32_t* sB = gsm + 64 * GASTR;

    const int tid  = threadIdx.x;
    const int wid  = tid >> 5;
    const int lane = tid & 31;
    const int N = H_;

    const float* A; const float* Bm; const float* bias; float* C;
    int M, mb;
    if (blockIdx.y < NB1) {
        A = A1; Bm = B1; bias = bias1; C = C1; M = M1; mb = blockIdx.y * 64;
    } else {
        A = A2; Bm = B2; bias = nullptr; C = C2; M = M2; mb = (blockIdx.y - NB1) * 64;
    }
    const int nb = blockIdx.x * 64;

    for (int i = tid; i < 64 * 64; i += 512) {
        int r  = i >> 6;
        int k4 = i & 63;
        int gm = mb + r;
        float4 v = make_float4(0.f, 0.f, 0.f, 0.f);
        if (gm < M) v = *(const float4*)(A + (size_t)gm * 256 + k4 * 4);
        sA[r * GASTR + k4 * 2]     = pack_bf16x2(v.x, v.y);
        sA[r * GASTR + k4 * 2 + 1] = pack_bf16x2(v.z, v.w);
    }
    for (int i = tid; i < 128 * 16; i += 512) {
        int k2 = i >> 4;
        int n4 = (i & 15) * 4;
        const float* p0 = Bm + (size_t)(2 * k2) * N + nb + n4;
        float4 r0 = *(const float4*)p0;
        float4 r1 = *(const float4*)(p0 + N);
        sB[(n4 + 0) * GASTR + k2] = pack_bf16x2(r0.x, r1.x);
        sB[(n4 + 1) * GASTR + k2] = pack_bf16x2(r0.y, r1.y);
        sB[(n4 + 2) * GASTR + k2] = pack_bf16x2(r0.z, r1.z);
        sB[(n4 + 3) * GASTR + k2] = pack_bf16x2(r0.w, r1.w);
    }
    __syncthreads();

    const int gr = lane >> 2;
    const int c  = lane & 3;
    const int mrow = (wid & 3) * 16;
    const int nq   = (wid >> 2) * 2;      // n-tile base: 0,2,4,6
    const uint32_t* pa  = sA + (mrow + gr) * GASTR;
    const uint32_t* pa8 = pa + 8 * GASTR;
    const uint32_t* pbn = sB + gr * GASTR + nq * 8 * GASTR;

    float d0[2], d1[2], d2[2], d3[2];
    #pragma unroll
    for (int nt = 0; nt < 2; nt++) { d0[nt] = d1[nt] = d2[nt] = d3[nt] = 0.f; }

    #pragma unroll 4
    for (int ch = 0; ch < 16; ch++) {
        int k2b = ch * 8;
        uint32_t a0 = pa[k2b + c];
        uint32_t a1 = pa8[k2b + c];
        uint32_t a2 = pa[k2b + 4 + c];
        uint32_t a3 = pa8[k2b + 4 + c];
        #pragma unroll
        for (int nt = 0; nt < 2; nt++) {
            uint32_t b0 = pbn[nt * 8 * GASTR + k2b + c];
            uint32_t b1 = pbn[nt * 8 * GASTR + k2b + 4 + c];
            mma_bf16(d0[nt], d1[nt], d2[nt], d3[nt], a0, a1, a2, a3, b0, b1);
        }
    }

    int gm0 = mb + mrow + gr;
    int gm1 = gm0 + 8;
    #pragma unroll
    for (int nt = 0; nt < 2; nt++) {
        int gn = nb + (nq + nt) * 8 + 2 * c;
        float bb0 = bias ? bias[gn]     : 0.f;
        float bb1 = bias ? bias[gn + 1] : 0.f;
        if (gm0 < M) *(float2*)(C + (size_t)gm0 * N + gn) = make_float2(d0[nt] + bb0, d1[nt] + bb1);
        if (gm1 < M) *(float2*)(C + (size_t)gm1 * N + gn) = make_float2(d2[nt] + bb0, d3[nt] + bb1);
    }
}

// ---------------------------------------------------------------------------
// HMMA joint kernel — persistent multi-tile: grid (17, 8) = 136 blocks.
// Each block stages G + Wp once, then loops over up to 3 t-tiles (8 t each),
// re-staging only the F slice per tile. 512 threads / 16 warps.
// ---------------------------------------------------------------------------
__global__ void __launch_bounds__(512)
joint_hmma_kernel(const float* __restrict__ Wp,
                  const float* __restrict__ bp,
                  const int*  __restrict__ targets)
{
    extern __shared__ char smraw[];
    float*    sG  = (float*)(smraw + SM_G);
    float*    sF  = (float*)(smraw + SM_F);
    uint32_t* sBf = (uint32_t*)(smraw + SM_BF);
    float*    sD  = (float*)(smraw + SM_D);
    float*    sBp = (float*)(smraw + SM_BP);

    const int b    = blockIdx.y;
    const int tid  = threadIdx.x;
    const int wid  = tid >> 5;
    const int lane = tid & 31;

    const float* Gb = g_G + (size_t)b * U1_ * H_;

    if (tid < V_) sBp[tid] = bp[tid];

    // stage G once: 61x512 -> 64x516 (rows 61..63 zero)
    for (int i = tid; i < 64 * (H_ / 4); i += 512) {
        int r = i >> 7;
        int cc = (i & 127) << 2;
        float4 v4 = make_float4(0.f, 0.f, 0.f, 0.f);
        if (r < U1_) v4 = *(const float4*)(Gb + (size_t)r * H_ + cc);
        *(float4*)&sG[r * GSTR + cc] = v4;
    }
    // stage Wp fragments once
    for (int i = tid; i < 32 * 4 * 32; i += 512) {
        int ch = i >> 7;
        int nt = (i >> 5) & 3;
        int l  = i & 31;
        int kA = ch * 16 + 2 * (l & 3);
        int n  = nt * 8 + (l >> 2);
        uint32_t b0 = 0, b1 = 0;
        if (n < V_) {
            b0 = pack_bf16x2(Wp[(size_t)kA * V_ + n],       Wp[(size_t)(kA + 1) * V_ + n]);
            b1 = pack_bf16x2(Wp[(size_t)(kA + 8) * V_ + n], Wp[(size_t)(kA + 9) * V_ + n]);
        }
        sBf[(size_t)i * 2 + 0] = b0;
        sBf[(size_t)i * 2 + 1] = b1;
    }

    const int s    = wid & 3;
    const int tsub = wid >> 2;            // 0..3
    const int u0   = s * 16;
    const int gr    = lane >> 2;
    const int cbase = (lane & 3) * 2;

    const float* gRowA = sG + (u0 + gr) * GSTR;
    const float* gRowB = sG + (u0 + gr + 8) * GSTR;
    float* sDw = sD + wid * (16 * DSTR);

    const int tgt_u = (u0 + lane < U_) ? 1 : 0;   // placeholder to keep regs low
    (void)tgt_u;

    for (int tt = 0; tt < 3; tt++) {
        const int tile = blockIdx.x + tt * JGX;
        if (tile >= JTILES) break;
        const int tbase = tile * 8;
        const float* Fb = g_F + (size_t)(b * T_ + tbase) * H_;

        __syncthreads();   // previous tile's readers done before overwriting sF
        for (int i = tid; i < 8 * (H_ / 4); i += 512) {
            int r = i >> 7;
            int cc = (i & 127) << 2;
            *(float4*)&sF[r * H_ + cc] = *(const float4*)(Fb + (size_t)r * H_ + cc);
        }
        __syncthreads();

        #pragma unroll 1
        for (int it = 0; it < 2; it++) {
            const int tloc = tsub * 2 + it;
            const float* fRow = sF + tloc * H_;

            float d0[4], d1[4], d2[4], d3[4];
            #pragma unroll
            for (int nt = 0; nt < 4; nt++) { d0[nt] = d1[nt] = d2[nt] = d3[nt] = 0.f; }

            #pragma unroll 2
            for (int ch = 0; ch < 32; ch++) {
                int k = ch * 16 + cbase;
                float2 fA  = *(const float2*)(fRow  + k);
                float2 fB  = *(const float2*)(fRow  + k + 8);
                float2 gAa = *(const float2*)(gRowA + k);
                float2 gBa = *(const float2*)(gRowA + k + 8);
                float2 gAb = *(const float2*)(gRowB + k);
                float2 gBb = *(const float2*)(gRowB + k + 8);
                uint32_t a0 = pack_bf16x2(fast_tanh(fA.x + gAa.x), fast_tanh(fA.y + gAa.y));
                uint32_t a1 = pack_bf16x2(fast_tanh(fA.x + gAb.x), fast_tanh(fA.y + gAb.y));
                uint32_t a2 = pack_bf16x2(fast_tanh(fB.x + gBa.x), fast_tanh(fB.y + gBa.y));
                uint32_t a3 = pack_bf16x2(fast_tanh(fB.x + gBb.x), fast_tanh(fB.y + gBb.y));
                const uint32_t* bf = sBf + (size_t)(ch * 4) * 64 + lane * 2;
                #pragma unroll
                for (int nt = 0; nt < 4; nt++) {
                    uint32_t bb0 = bf[nt * 64 + 0];
                    uint32_t bb1 = bf[nt * 64 + 1];
                    mma_bf16(d0[nt], d1[nt], d2[nt], d3[nt], a0, a1, a2, a3, bb0, bb1);
                }
            }

            #pragma unroll
            for (int nt = 0; nt < 4; nt++) {
                int cc = nt * 8 + cbase;
                *(float2*)&sDw[gr * DSTR + cc]       = make_float2(d0[nt], d1[nt]);
                *(float2*)&sDw[(gr + 8) * DSTR + cc] = make_float2(d2[nt], d3[nt]);
            }
            __syncwarp();

            if (lane < 16) {
                int u = u0 + lane;
                if (u < U1_) {
                    int t = tbase + tloc;
                    float logits[V_];
                    float m = -1e30f;
                    #pragma unroll
                    for (int v = 0; v < V_; v++) {
                        logits[v] = sDw[lane * DSTR + v] + sBp[v];
                        m = fmaxf(m, logits[v]);
                    }
                    float ssum = 0.f;
                    #pragma unroll
                    for (int v = 0; v < V_; v++) ssum += fast_ex2((logits[v] - m) * LOG2E);
                    float lse = m + fast_lg2(ssum) * LN2;

                    int tgt = (u < U_) ? targets[b * U_ + u] : 0;
                    float lv = logits[0];
                    #pragma unroll
                    for (int v = 1; v < V_; v++)
                        if (v == tgt) lv = logits[v];

                    size_t idx = (size_t)(b * T_ + t) * U1_ + u;
                    g_blank[idx] = logits[BLANK_] - lse;
                    if (u < U_) g_lab[idx] = lv - lse;
                }
            }
            __syncwarp();
        }
    }
}

// ---------------------------------------------------------------------------
// Forward DP (R12: phase-split, 2 shfls/step, dcap-bounded). Unchanged.
// ---------------------------------------------------------------------------
__global__ void dp_kernel(const int* __restrict__ t_lens,
                          const int* __restrict__ u_lens,
                          float* __restrict__ out)
{
    extern __shared__ float sm[];
    float* sB = sm;
    float* sL = sm + T_ * U1_;

    int b   = blockIdx.x;
    int tid = threadIdx.x;

    const int Tl = t_lens[b], Ul = u_lens[b];
    const int dcap = (Tl - 1) + Ul;

    const float4* srcB = (const float4*)(g_blank + (size_t)b * T_ * U1_);
    const float4* srcL = (const float4*)(g_lab   + (size_t)b * T_ * U1_);
    const int nrows = min(T_, dcap + 2);
    const int n4 = (nrows * U1_ + 3) / 4;
    for (int i = tid; i < n4; i += 1024) {
        float4 vb = srcB[i];
        float4 vl = srcL[i];
        vb.x *= LOG2E; vb.y *= LOG2E; vb.z *= LOG2E; vb.w *= LOG2E;
        vl.x *= LOG2E; vl.y *= LOG2E; vl.z *= LOG2E; vl.w *= LOG2E;
        ((float4*)sB)[i] = vb;
        ((float4*)sL)[i] = vl;
    }
    __syncthreads();
    if (tid >= 32) return;

    const int lane = tid;
    const bool cap_lo = (Ul < 32) && (lane == Ul);
    const bool cap_hi = (Ul >= 32) && (lane == Ul - 32);
    const int srcl = (lane + 31) & 31;

    const int u_lo = lane;
    const int u_hi = lane + 32;
    const int ulo_m1 = max(u_lo - 1, 0);
    const int uhi_c  = min(u_hi, U1_ - 1);
    const int uhi_m1 = min(u_hi - 1, U1_ - 1);

    float a_lo = (lane == 0) ? 0.f : NEGF;
    float a_hi = NEGF;
    float res  = 0.f;

    for (int d = 1; d <= 63; d++) {
        float p_lo = __shfl_up_sync(0xffffffffu, a_lo, 1);
        p_lo = (lane == 0) ? NEGF : p_lo;
        float yh   = (lane == 31) ? a_lo : a_hi;
        float p_hi = __shfl_sync(0xffffffffu, yh, srcl);

        int t  = d - u_lo;
        int i1 = min(max(t - 1, 0), T_ - 1);
        int i2 = min(max(t, 0), T_ - 1);
        float v1 = a_lo + sB[i1 * U1_ + u_lo];
        float v2 = p_lo + sL[i2 * U1_ + ulo_m1];
        float mx = fmaxf(v1, v2), mn = fminf(v1, v2);
        a_lo = mx + fast_lg2(1.f + fast_ex2(mn - mx));

        int th = d - u_hi;
        int j1 = min(max(th - 1, 0), T_ - 1);
        int j2 = min(max(th, 0), T_ - 1);
        float w1 = a_hi + sB[j1 * U1_ + uhi_c];
        float w2 = p_hi + sL[j2 * U1_ + uhi_m1];
        float mxh = fmaxf(w1, w2), mnh = fminf(w1, w2);
        a_hi = mxh + fast_lg2(1.f + fast_ex2(mnh - mxh));
    }

    {
        const int d2end = min(399, dcap);
        int ob_lo = (63 - u_lo) * U1_ + u_lo;
        int ol_lo = (64 - u_lo) * U1_ + ulo_m1;
        int ob_hi = (63 - u_hi) * U1_ + uhi_c;
        int ol_hi = (64 - u_hi) * U1_ + uhi_m1;

        float Blo = sB[ob_lo], Llo = sL[ol_lo];
        float Bhi = sB[ob_hi], Lhi = sL[ol_hi];

        #pragma unroll 2
        for (int d = 64; d <= d2end; d++) {
            ob_lo += U1_; ol_lo += U1_; ob_hi += U1_; ol_hi += U1_;
            float nBlo = sB[ob_lo];
            float nLlo = sL[ol_lo];
            float nBhi = sB[ob_hi];
            float nLhi = sL[ol_hi];

            float p_lo = __shfl_up_sync(0xffffffffu, a_lo, 1);
            p_lo = (lane == 0) ? NEGF : p_lo;
            float yh   = (lane == 31) ? a_lo : a_hi;
            float p_hi = __shfl_sync(0xffffffffu, yh, srcl);

            float v1 = a_lo + Blo;
            float v2 = p_lo + Llo;
            float mx = fmaxf(v1, v2), mn = fminf(v1, v2);
            float n_lo = mx + fast_lg2(1.f + fast_ex2(mn - mx));

            float w1 = a_hi + Bhi;
            float w2 = p_hi + Lhi;
            float mxh = fmaxf(w1, w2), mnh = fminf(w1, w2);
            float n_hi = mxh + fast_lg2(1.f + fast_ex2(mnh - mxh));

            bool hit = (d == dcap);
            res = (hit && cap_lo) ? n_lo : res;
            res = (hit && cap_hi) ? n_hi : res;
            a_lo = n_lo;
            a_hi = n_hi;
            Blo = nBlo; Llo = nLlo; Bhi = nBhi; Lhi = nLhi;
        }
    }

    for (int d = 400; d <= dcap; d++) {
        float p_lo = __shfl_up_sync(0xffffffffu, a_lo, 1);
        p_lo = (lane == 0) ? NEGF : p_lo;
        float yh   = (lane == 31) ? a_lo : a_hi;
        float p_hi = __shfl_sync(0xffffffffu, yh, srcl);

        int t  = d - u_lo;
        int i1 = min(max(t - 1, 0), T_ - 1);
        int i2 = min(max(t, 0), T_ - 1);
        float v1 = a_lo + sB[i1 * U1_ + u_lo];
        float v2 = p_lo + sL[i2 * U1_ + ulo_m1];
        float mx = fmaxf(v1, v2), mn = fminf(v1, v2);
        float n_lo = mx + fast_lg2(1.f + fast_ex2(mn - mx));

        int th = d - u_hi;
        int j1 = min(max(th - 1, 0), T_ - 1);
        int j2 = min(max(th, 0), T_ - 1);
        float w1 = a_hi + sB[j1 * U1_ + uhi_c];
        float w2 = p_hi + sL[j2 * U1_ + uhi_m1];
        float mxh = fmaxf(w1, w2), mnh = fminf(w1, w2);
        float n_hi = mxh + fast_lg2(1.f + fast_ex2(mnh - mxh));

        bool hit = (d == dcap);
        res = (hit && cap_lo) ? n_lo : res;
        res = (hit && cap_hi) ? n_hi : res;
        a_lo = n_lo;
        a_hi = n_hi;
    }

    if (cap_lo || cap_hi) {
        float blank_fin = g_blank[(size_t)b * T_ * U1_ + (size_t)(Tl - 1) * U1_ + Ul];
        out[b] = -(res * LN2 + blank_fin);
    }
}

// ---------------------------------------------------------------------------
extern "C" void kernel_launch(void* const* d_in, const int* in_sizes, int n_in,
                              void* d_out, int out_size)
{
    const float* enc     = (const float*)d_in[0];
    const float* dec     = (const float*)d_in[1];
    const float* We      = (const float*)d_in[2];
    const float* Wd      = (const float*)d_in[3];
    const float* bf      = (const float*)d_in[4];
    const float* Wp      = (const float*)d_in[5];
    const float* bp      = (const float*)d_in[6];
    const int*   targets = (const int*)d_in[7];
    const int*   t_lens  = (const int*)d_in[8];
    const int*   u_lens  = (const int*)d_in[9];
    float* out = (float*)d_out;

    float *pF = nullptr, *pG = nullptr;
    cudaGetSymbolAddress((void**)&pF, g_F);
    cudaGetSymbolAddress((void**)&pG, g_G);

    static bool attr_set = false;
    if (!attr_set) {
        cudaFuncSetAttribute(dp_kernel,
                             cudaFuncAttributeMaxDynamicSharedMemorySize, DP_SMEM);
        cudaFuncSetAttribute(joint_hmma_kernel,
                             cudaFuncAttributeMaxDynamicSharedMemorySize, JSMEM);
        cudaFuncSetAttribute(gemm_hmma_kernel,
                             cudaFuncAttributeMaxDynamicSharedMemorySize, GEMM_SMEM);
        attr_set = true;
    }

    gemm_hmma_kernel<<<dim3(H_ / 64, NB1 + NB2), 512, GEMM_SMEM>>>(
        enc, dec, We, Wd, bf, pF, pG, B_ * T_, B_ * U1_);
    joint_hmma_kernel<<<dim3(JGX, B_), 512, JSMEM>>>(Wp, bp, targets);
    dp_kernel<<<B_, 1024, DP_SMEM>>>(t_lens, u_lens, out);
}

// round 15
// speedup vs baseline: 1.5504x; 1.1867x over previous
#include <cuda_runtime.h>
#include <cuda_bf16.h>
#include <cstdint>

#define B_    8
#define T_    400
#define U_    60
#define U1_   61
#define E_    256
#define H_    512
#define V_    28
#define BLANK_ 27
#define NEGF  (-1e30f)
#define LOG2E 1.4426950408889634f
#define LN2   0.6931471805599453f

// joint smem layout (bytes) — bf16 F/G version
#define GSTRH  260                            // G/F row stride in u32 (256 + 4 pad)
#define DSTR   34
#define SM_G   0                              // 64*260*4  = 66560
#define SM_F   66560                          // 8*260*4   = 8320
#define SM_BF  74880                          // 32*4*32*8 = 32768
#define SM_D   107648                         // 16*16*34*4= 34816
#define SM_BP  142464                         // 128
#define JSMEM  142592

// joint tiling: 50 t-tiles of 8, grid.x=17, each block does <=3 tiles
#define JTILES 50
#define JGX    17

// gemm smem
#define GASTR  132
#define GEMM_SMEM (2 * 64 * GASTR * 4)
#define NB1    50
#define NB2    8

// dp smem: 2*T*U1 floats + 128 pad (prefetch overrun)
#define DP_SMEM ((2 * T_ * U1_ + 128) * 4)

// Scratch (no cudaMalloc allowed)
__device__ float g_F[B_*T_*H_];
__device__ float g_G[B_*U1_*H_];
__device__ float g_blank[B_*T_*U1_];
__device__ float g_lab[B_*T_*U1_];

__device__ __forceinline__ float fast_ex2(float x) {
    float y; asm("ex2.approx.f32 %0, %1;" : "=f"(y) : "f"(x)); return y;
}
__device__ __forceinline__ float fast_lg2(float x) {
    float y; asm("lg2.approx.f32 %0, %1;" : "=f"(y) : "f"(x)); return y;
}
__device__ __forceinline__ uint32_t pack_bf16x2(float lo, float hi) {
    uint32_t r;
    asm("cvt.rn.bf16x2.f32 %0, %1, %2;" : "=r"(r) : "f"(hi), "f"(lo));
    return r;
}
__device__ __forceinline__ uint32_t hadd2_bf16(uint32_t a, uint32_t b) {
    uint32_t d;
    asm("add.rn.bf16x2 %0, %1, %2;" : "=r"(d) : "r"(a), "r"(b));
    return d;
}
__device__ __forceinline__ uint32_t tanh2_bf16(uint32_t a) {
    uint32_t d;
    asm("tanh.approx.bf16x2 %0, %1;" : "=r"(d) : "r"(a));
    return d;
}
__device__ __forceinline__ void mma_bf16(float& d0, float& d1, float& d2, float& d3,
                                         uint32_t a0, uint32_t a1, uint32_t a2, uint32_t a3,
                                         uint32_t b0, uint32_t b1) {
    asm("mma.sync.aligned.m16n8k16.row.col.f32.bf16.bf16.f32 "
        "{%0,%1,%2,%3}, {%4,%5,%6,%7}, {%8,%9}, {%0,%1,%2,%3};"
        : "+f"(d0), "+f"(d1), "+f"(d2), "+f"(d3)
        : "r"(a0), "r"(a1), "r"(a2), "r"(a3), "r"(b0), "r"(b1));
}

// ---------------------------------------------------------------------------
// Merged bf16 HMMA GEMM, 512 threads (16 warps) — unchanged from R14.
// ---------------------------------------------------------------------------
__global__ void __launch_bounds__(512)
gemm_hmma_kernel(const float* __restrict__ A1,
                 const float* __restrict__ A2,
                 const float* __restrict__ B1,
                 const float* __restrict__ B2,
                 const float* __restrict__ bias1,
                 float* __restrict__ C1,
                 float* __restrict__ C2,
                 int M1, int M2)
{
    extern __shared__ uint32_t gsm[];
    uint32_t* sA = gsm;
    uint32_t* sB = gsm + 64 * GASTR;

    const int tid  = threadIdx.x;
    const int wid  = tid >> 5;
    const int lane = tid & 31;
    const int N = H_;

    const float* A; const float* Bm; const float* bias; float* C;
    int M, mb;
    if (blockIdx.y < NB1) {
        A = A1; Bm = B1; bias = bias1; C = C1; M = M1; mb = blockIdx.y * 64;
    } else {
        A = A2; Bm = B2; bias = nullptr; C = C2; M = M2; mb = (blockIdx.y - NB1) * 64;
    }
    const int nb = blockIdx.x * 64;

    for (int i = tid; i < 64 * 64; i += 512) {
        int r  = i >> 6;
        int k4 = i & 63;
        int gm = mb + r;
        float4 v = make_float4(0.f, 0.f, 0.f, 0.f);
        if (gm < M) v = *(const float4*)(A + (size_t)gm * 256 + k4 * 4);
        sA[r * GASTR + k4 * 2]     = pack_bf16x2(v.x, v.y);
        sA[r * GASTR + k4 * 2 + 1] = pack_bf16x2(v.z, v.w);
    }
    for (int i = tid; i < 128 * 16; i += 512) {
        int k2 = i >> 4;
        int n4 = (i & 15) * 4;
        const float* p0 = Bm + (size_t)(2 * k2) * N + nb + n4;
        float4 r0 = *(const float4*)p0;
        float4 r1 = *(const float4*)(p0 + N);
        sB[(n4 + 0) * GASTR + k2] = pack_bf16x2(r0.x, r1.x);
        sB[(n4 + 1) * GASTR + k2] = pack_bf16x2(r0.y, r1.y);
        sB[(n4 + 2) * GASTR + k2] = pack_bf16x2(r0.z, r1.z);
        sB[(n4 + 3) * GASTR + k2] = pack_bf16x2(r0.w, r1.w);
    }
    __syncthreads();

    const int gr = lane >> 2;
    const int c  = lane & 3;
    const int mrow = (wid & 3) * 16;
    const int nq   = (wid >> 2) * 2;
    const uint32_t* pa  = sA + (mrow + gr) * GASTR;
    const uint32_t* pa8 = pa + 8 * GASTR;
    const uint32_t* pbn = sB + gr * GASTR + nq * 8 * GASTR;

    float d0[2], d1[2], d2[2], d3[2];
    #pragma unroll
    for (int nt = 0; nt < 2; nt++) { d0[nt] = d1[nt] = d2[nt] = d3[nt] = 0.f; }

    #pragma unroll 4
    for (int ch = 0; ch < 16; ch++) {
        int k2b = ch * 8;
        uint32_t a0 = pa[k2b + c];
        uint32_t a1 = pa8[k2b + c];
        uint32_t a2 = pa[k2b + 4 + c];
        uint32_t a3 = pa8[k2b + 4 + c];
        #pragma unroll
        for (int nt = 0; nt < 2; nt++) {
            uint32_t b0 = pbn[nt * 8 * GASTR + k2b + c];
            uint32_t b1 = pbn[nt * 8 * GASTR + k2b + 4 + c];
            mma_bf16(d0[nt], d1[nt], d2[nt], d3[nt], a0, a1, a2, a3, b0, b1);
        }
    }

    int gm0 = mb + mrow + gr;
    int gm1 = gm0 + 8;
    #pragma unroll
    for (int nt = 0; nt < 2; nt++) {
        int gn = nb + (nq + nt) * 8 + 2 * c;
        float bb0 = bias ? bias[gn]     : 0.f;
        float bb1 = bias ? bias[gn + 1] : 0.f;
        if (gm0 < M) *(float2*)(C + (size_t)gm0 * N + gn) = make_float2(d0[nt] + bb0, d1[nt] + bb1);
        if (gm1 < M) *(float2*)(C + (size_t)gm1 * N + gn) = make_float2(d2[nt] + bb0, d3[nt] + bb1);
    }
}

// ---------------------------------------------------------------------------
// HMMA joint kernel — persistent multi-tile + bf16 F/G with tanh.approx.bf16x2.
// Grid (17, 8), 512 threads. Per chunk: 6 LDS.32, 4 HADD2, 4 MUFU (x2 elems),
// zero CVT; A-fragments come out pre-packed.
// ---------------------------------------------------------------------------
__global__ void __launch_bounds__(512)
joint_hmma_kernel(const float* __restrict__ Wp,
                  const float* __restrict__ bp,
                  const int*  __restrict__ targets)
{
    extern __shared__ char smraw[];
    uint32_t* sGh = (uint32_t*)(smraw + SM_G);    // [64][260] bf16x2 pairs
    uint32_t* sFh = (uint32_t*)(smraw + SM_F);    // [8][260]
    uint32_t* sBf = (uint32_t*)(smraw + SM_BF);
    float*    sD  = (float*)(smraw + SM_D);
    float*    sBp = (float*)(smraw + SM_BP);

    const int b    = blockIdx.y;
    const int tid  = threadIdx.x;
    const int wid  = tid >> 5;
    const int lane = tid & 31;

    const float* Gb = g_G + (size_t)b * U1_ * H_;

    if (tid < V_) sBp[tid] = bp[tid];

    // stage G once as bf16: 61x512 -> 64 rows x 256 u32 (rows 61..63 zero)
    for (int i = tid; i < 64 * 128; i += 512) {
        int r  = i >> 7;
        int q  = i & 127;                 // float4 group
        float4 v = make_float4(0.f, 0.f, 0.f, 0.f);
        if (r < U1_) v = *(const float4*)(Gb + (size_t)r * H_ + q * 4);
        sGh[r * GSTRH + q * 2]     = pack_bf16x2(v.x, v.y);
        sGh[r * GSTRH + q * 2 + 1] = pack_bf16x2(v.z, v.w);
    }
    // stage Wp fragments once
    for (int i = tid; i < 32 * 4 * 32; i += 512) {
        int ch = i >> 7;
        int nt = (i >> 5) & 3;
        int l  = i & 31;
        int kA = ch * 16 + 2 * (l & 3);
        int n  = nt * 8 + (l >> 2);
        uint32_t b0 = 0, b1 = 0;
        if (n < V_) {
            b0 = pack_bf16x2(Wp[(size_t)kA * V_ + n],       Wp[(size_t)(kA + 1) * V_ + n]);
            b1 = pack_bf16x2(Wp[(size_t)(kA + 8) * V_ + n], Wp[(size_t)(kA + 9) * V_ + n]);
        }
        sBf[(size_t)i * 2 + 0] = b0;
        sBf[(size_t)i * 2 + 1] = b1;
    }

    const int s    = wid & 3;
    const int tsub = wid >> 2;            // 0..3
    const int u0   = s * 16;
    const int gr    = lane >> 2;
    const int c4    = lane & 3;

    const uint32_t* gA = sGh + (u0 + gr) * GSTRH;       // row u0+gr
    const uint32_t* gB = gA + 8 * GSTRH;                // row u0+gr+8
    float* sDw = sD + wid * (16 * DSTR);

    for (int tt = 0; tt < 3; tt++) {
        const int tile = blockIdx.x + tt * JGX;
        if (tile >= JTILES) break;
        const int tbase = tile * 8;
        const float* Fb = g_F + (size_t)(b * T_ + tbase) * H_;

        __syncthreads();   // previous tile's readers done before overwriting sF
        for (int i = tid; i < 8 * 128; i += 512) {
            int r = i >> 7;
            int q = i & 127;
            float4 v = *(const float4*)(Fb + (size_t)r * H_ + q * 4);
            sFh[r * GSTRH + q * 2]     = pack_bf16x2(v.x, v.y);
            sFh[r * GSTRH + q * 2 + 1] = pack_bf16x2(v.z, v.w);
        }
        __syncthreads();

        #pragma unroll 1
        for (int it = 0; it < 2; it++) {
            const int tloc = tsub * 2 + it;
            const uint32_t* fR = sFh + tloc * GSTRH;

            float d0[4], d1[4], d2[4], d3[4];
            #pragma unroll
            for (int nt = 0; nt < 4; nt++) { d0[nt] = d1[nt] = d2[nt] = d3[nt] = 0.f; }

            #pragma unroll 2
            for (int ch = 0; ch < 32; ch++) {
                int idx = ch * 8 + c4;           // u32 index: pair (k, k+1)
                uint32_t fv0 = fR[idx];
                uint32_t fv1 = fR[idx + 4];
                uint32_t a0 = tanh2_bf16(hadd2_bf16(fv0, gA[idx]));
                uint32_t a1 = tanh2_bf16(hadd2_bf16(fv0, gB[idx]));
                uint32_t a2 = tanh2_bf16(hadd2_bf16(fv1, gA[idx + 4]));
                uint32_t a3 = tanh2_bf16(hadd2_bf16(fv1, gB[idx + 4]));
                const uint32_t* bf = sBf + (size_t)(ch * 4) * 64 + lane * 2;
                #pragma unroll
                for (int nt = 0; nt < 4; nt++) {
                    uint32_t bb0 = bf[nt * 64 + 0];
                    uint32_t bb1 = bf[nt * 64 + 1];
                    mma_bf16(d0[nt], d1[nt], d2[nt], d3[nt], a0, a1, a2, a3, bb0, bb1);
                }
            }

            const int cbase = c4 * 2;
            #pragma unroll
            for (int nt = 0; nt < 4; nt++) {
                int cc = nt * 8 + cbase;
                *(float2*)&sDw[gr * DSTR + cc]       = make_float2(d0[nt], d1[nt]);
                *(float2*)&sDw[(gr + 8) * DSTR + cc] = make_float2(d2[nt], d3[nt]);
            }
            __syncwarp();

            if (lane < 16) {
                int u = u0 + lane;
                if (u < U1_) {
                    int t = tbase + tloc;
                    float logits[V_];
                    float m = -1e30f;
                    #pragma unroll
                    for (int v = 0; v < V_; v++) {
                        logits[v] = sDw[lane * DSTR + v] + sBp[v];
                        m = fmaxf(m, logits[v]);
                    }
                    float ssum = 0.f;
                    #pragma unroll
                    for (int v = 0; v < V_; v++) ssum += fast_ex2((logits[v] - m) * LOG2E);
                    float lse = m + fast_lg2(ssum) * LN2;

                    int tgt = (u < U_) ? targets[b * U_ + u] : 0;
                    float lv = logits[0];
                    #pragma unroll
                    for (int v = 1; v < V_; v++)
                        if (v == tgt) lv = logits[v];

                    size_t idx2 = (size_t)(b * T_ + t) * U1_ + u;
                    g_blank[idx2] = logits[BLANK_] - lse;
                    if (u < U_) g_lab[idx2] = lv - lse;
                }
            }
            __syncwarp();
        }
    }
}

// ---------------------------------------------------------------------------
// Forward DP (unchanged).
// ---------------------------------------------------------------------------
__global__ void dp_kernel(const int* __restrict__ t_lens,
                          const int* __restrict__ u_lens,
                          float* __restrict__ out)
{
    extern __shared__ float sm[];
    float* sB = sm;
    float* sL = sm + T_ * U1_;

    int b   = blockIdx.x;
    int tid = threadIdx.x;

    const int Tl = t_lens[b], Ul = u_lens[b];
    const int dcap = (Tl - 1) + Ul;

    const float4* srcB = (const float4*)(g_blank + (size_t)b * T_ * U1_);
    const float4* srcL = (const float4*)(g_lab   + (size_t)b * T_ * U1_);
    const int nrows = min(T_, dcap + 2);
    const int n4 = (nrows * U1_ + 3) / 4;
    for (int i = tid; i < n4; i += 1024) {
        float4 vb = srcB[i];
        float4 vl = srcL[i];
        vb.x *= LOG2E; vb.y *= LOG2E; vb.z *= LOG2E; vb.w *= LOG2E;
        vl.x *= LOG2E; vl.y *= LOG2E; vl.z *= LOG2E; vl.w *= LOG2E;
        ((float4*)sB)[i] = vb;
        ((float4*)sL)[i] = vl;
    }
    __syncthreads();
    if (tid >= 32) return;

    const int lane = tid;
    const bool cap_lo = (Ul < 32) && (lane == Ul);
    const bool cap_hi = (Ul >= 32) && (lane == Ul - 32);
    const int srcl = (lane + 31) & 31;

    const int u_lo = lane;
    const int u_hi = lane + 32;
    const int ulo_m1 = max(u_lo - 1, 0);
    const int uhi_c  = min(u_hi, U1_ - 1);
    const int uhi_m1 = min(u_hi - 1, U1_ - 1);

    float a_lo = (lane == 0) ? 0.f : NEGF;
    float a_hi = NEGF;
    float res  = 0.f;

    for (int d = 1; d <= 63; d++) {
        float p_lo = __shfl_up_sync(0xffffffffu, a_lo, 1);
        p_lo = (lane == 0) ? NEGF : p_lo;
        float yh   = (lane == 31) ? a_lo : a_hi;
        float p_hi = __shfl_sync(0xffffffffu, yh, srcl);

        int t  = d - u_lo;
        int i1 = min(max(t - 1, 0), T_ - 1);
        int i2 = min(max(t, 0), T_ - 1);
        float v1 = a_lo + sB[i1 * U1_ + u_lo];
        float v2 = p_lo + sL[i2 * U1_ + ulo_m1];
        float mx = fmaxf(v1, v2), mn = fminf(v1, v2);
        a_lo = mx + fast_lg2(1.f + fast_ex2(mn - mx));

        int th = d - u_hi;
        int j1 = min(max(th - 1, 0), T_ - 1);
        int j2 = min(max(th, 0), T_ - 1);
        float w1 = a_hi + sB[j1 * U1_ + uhi_c];
        float w2 = p_hi + sL[j2 * U1_ + uhi_m1];
        float mxh = fmaxf(w1, w2), mnh = fminf(w1, w2);
        a_hi = mxh + fast_lg2(1.f + fast_ex2(mnh - mxh));
    }

    {
        const int d2end = min(399, dcap);
        int ob_lo = (63 - u_lo) * U1_ + u_lo;
        int ol_lo = (64 - u_lo) * U1_ + ulo_m1;
        int ob_hi = (63 - u_hi) * U1_ + uhi_c;
        int ol_hi = (64 - u_hi) * U1_ + uhi_m1;

        float Blo = sB[ob_lo], Llo = sL[ol_lo];
        float Bhi = sB[ob_hi], Lhi = sL[ol_hi];

        #pragma unroll 2
        for (int d = 64; d <= d2end; d++) {
            ob_lo += U1_; ol_lo += U1_; ob_hi += U1_; ol_hi += U1_;
            float nBlo = sB[ob_lo];
            float nLlo = sL[ol_lo];
            float nBhi = sB[ob_hi];
            float nLhi = sL[ol_hi];

            float p_lo = __shfl_up_sync(0xffffffffu, a_lo, 1);
            p_lo = (lane == 0) ? NEGF : p_lo;
            float yh   = (lane == 31) ? a_lo : a_hi;
            float p_hi = __shfl_sync(0xffffffffu, yh, srcl);

            float v1 = a_lo + Blo;
            float v2 = p_lo + Llo;
            float mx = fmaxf(v1, v2), mn = fminf(v1, v2);
            float n_lo = mx + fast_lg2(1.f + fast_ex2(mn - mx));

            float w1 = a_hi + Bhi;
            float w2 = p_hi + Lhi;
            float mxh = fmaxf(w1, w2), mnh = fminf(w1, w2);
            float n_hi = mxh + fast_lg2(1.f + fast_ex2(mnh - mxh));

            bool hit = (d == dcap);
            res = (hit && cap_lo) ? n_lo : res;
            res = (hit && cap_hi) ? n_hi : res;
            a_lo = n_lo;
            a_hi = n_hi;
            Blo = nBlo; Llo = nLlo; Bhi = nBhi; Lhi = nLhi;
        }
    }

    for (int d = 400; d <= dcap; d++) {
        float p_lo = __shfl_up_sync(0xffffffffu, a_lo, 1);
        p_lo = (lane == 0) ? NEGF : p_lo;
        float yh   = (lane == 31) ? a_lo : a_hi;
        float p_hi = __shfl_sync(0xffffffffu, yh, srcl);

        int t  = d - u_lo;
        int i1 = min(max(t - 1, 0), T_ - 1);
        int i2 = min(max(t, 0), T_ - 1);
        float v1 = a_lo + sB[i1 * U1_ + u_lo];
        float v2 = p_lo + sL[i2 * U1_ + ulo_m1];
        float mx = fmaxf(v1, v2), mn = fminf(v1, v2);
        float n_lo = mx + fast_lg2(1.f + fast_ex2(mn - mx));

        int th = d - u_hi;
        int j1 = min(max(th - 1, 0), T_ - 1);
        int j2 = min(max(th, 0), T_ - 1);
        float w1 = a_hi + sB[j1 * U1_ + uhi_c];
        float w2 = p_hi + sL[j2 * U1_ + uhi_m1];
        float mxh = fmaxf(w1, w2), mnh = fminf(w1, w2);
        float n_hi = mxh + fast_lg2(1.f + fast_ex2(mnh - mxh));

        bool hit = (d == dcap);
        res = (hit && cap_lo) ? n_lo : res;
        res = (hit && cap_hi) ? n_hi : res;
        a_lo = n_lo;
        a_hi = n_hi;
    }

    if (cap_lo || cap_hi) {
        float blank_fin = g_blank[(size_t)b * T_ * U1_ + (size_t)(Tl - 1) * U1_ + Ul];
        out[b] = -(res * LN2 + blank_fin);
    }
}

// ---------------------------------------------------------------------------
extern "C" void kernel_launch(void* const* d_in, const int* in_sizes, int n_in,
                              void* d_out, int out_size)
{
    const float* enc     = (const float*)d_in[0];
    const float* dec     = (const float*)d_in[1];
    const float* We      = (const float*)d_in[2];
    const float* Wd      = (const float*)d_in[3];
    const float* bf      = (const float*)d_in[4];
    const float* Wp      = (const float*)d_in[5];
    const float* bp      = (const float*)d_in[6];
    const int*   targets = (const int*)d_in[7];
    const int*   t_lens  = (const int*)d_in[8];
    const int*   u_lens  = (const int*)d_in[9];
    float* out = (float*)d_out;

    float *pF = nullptr, *pG = nullptr;
    cudaGetSymbolAddress((void**)&pF, g_F);
    cudaGetSymbolAddress((void**)&pG, g_G);

    static bool attr_set = false;
    if (!attr_set) {
        cudaFuncSetAttribute(dp_kernel,
                             cudaFuncAttributeMaxDynamicSharedMemorySize, DP_SMEM);
        cudaFuncSetAttribute(joint_hmma_kernel,
                             cudaFuncAttributeMaxDynamicSharedMemorySize, JSMEM);
        cudaFuncSetAttribute(gemm_hmma_kernel,
                             cudaFuncAttributeMaxDynamicSharedMemorySize, GEMM_SMEM);
        attr_set = true;
    }

    gemm_hmma_kernel<<<dim3(H_ / 64, NB1 + NB2), 512, GEMM_SMEM>>>(
        enc, dec, We, Wd, bf, pF, pG, B_ * T_, B_ * U1_);
    joint_hmma_kernel<<<dim3(JGX, B_), 512, JSMEM>>>(Wp, bp, targets);
    dp_kernel<<<B_, 1024, DP_SMEM>>>(t_lens, u_lens, out);
}

// round 16
// speedup vs baseline: 1.5515x; 1.0007x over previous
#include <cuda_runtime.h>
#include <cuda_bf16.h>
#include <cstdint>

#define B_    8
#define T_    400
#define U_    60
#define U1_   61
#define E_    256
#define H_    512
#define H2_   256                             // H/2 bf16x2 pairs per row
#define V_    28
#define BLANK_ 27
#define NEGF  (-1e30f)
#define LOG2E 1.4426950408889634f
#define LN2   0.6931471805599453f

// joint smem layout (bytes) — bf16 F/G version
#define GSTRH  260                            // G/F row stride in u32 (256 + 4 pad)
#define DSTR   34
#define SM_G   0                              // 64*260*4  = 66560
#define SM_F   66560                          // 8*260*4   = 8320
#define SM_BF  74880                          // 32*4*32*8 = 32768
#define SM_D   107648                         // 16*16*34*4= 34816
#define SM_BP  142464                         // 128
#define JSMEM  142592

// joint tiling: 50 t-tiles of 8, grid.x=17, each block does <=3 tiles
#define JTILES 50
#define JGX    17

// gemm smem: sA 64x132 u32 + sB 128x132 u32
#define GASTR  132
#define GEMM_SMEM ((64 + 128) * GASTR * 4)
#define NB1    50
#define NB2    8

// dp smem: 2*T*U1 floats + 128 pad (prefetch overrun)
#define DP_SMEM ((2 * T_ * U1_ + 128) * 4)

// Scratch (no cudaMalloc allowed) — F/G stored as packed bf16x2
__device__ uint32_t g_F[B_*T_*H2_];
__device__ uint32_t g_G[B_*U1_*H2_];
__device__ float g_blank[B_*T_*U1_];
__device__ float g_lab[B_*T_*U1_];

__device__ __forceinline__ float fast_ex2(float x) {
    float y; asm("ex2.approx.f32 %0, %1;" : "=f"(y) : "f"(x)); return y;
}
__device__ __forceinline__ float fast_lg2(float x) {
    float y; asm("lg2.approx.f32 %0, %1;" : "=f"(y) : "f"(x)); return y;
}
__device__ __forceinline__ uint32_t pack_bf16x2(float lo, float hi) {
    uint32_t r;
    asm("cvt.rn.bf16x2.f32 %0, %1, %2;" : "=r"(r) : "f"(hi), "f"(lo));
    return r;
}
__device__ __forceinline__ uint32_t hadd2_bf16(uint32_t a, uint32_t b) {
    uint32_t d;
    asm("add.rn.bf16x2 %0, %1, %2;" : "=r"(d) : "r"(a), "r"(b));
    return d;
}
__device__ __forceinline__ uint32_t tanh2_bf16(uint32_t a) {
    uint32_t d;
    asm("tanh.approx.bf16x2 %0, %1;" : "=r"(d) : "r"(a));
    return d;
}
__device__ __forceinline__ void mma_bf16(float& d0, float& d1, float& d2, float& d3,
                                         uint32_t a0, uint32_t a1, uint32_t a2, uint32_t a3,
                                         uint32_t b0, uint32_t b1) {
    asm("mma.sync.aligned.m16n8k16.row.col.f32.bf16.bf16.f32 "
        "{%0,%1,%2,%3}, {%4,%5,%6,%7}, {%8,%9}, {%0,%1,%2,%3};"
        : "+f"(d0), "+f"(d1), "+f"(d2), "+f"(d3)
        : "r"(a0), "r"(a1), "r"(a2), "r"(a3), "r"(b0), "r"(b1));
}

// ---------------------------------------------------------------------------
// Merged bf16 HMMA GEMM, 512 threads, tile 64m x 128n, K=256 smem-resident.
// grid (4, 58). Output written as packed bf16x2 (identical rounding to the
// old joint-side conversion). Warp w: m-strip (w&3)*16, n-tiles (w>>2)*4..+3.
// ---------------------------------------------------------------------------
__global__ void __launch_bounds__(512)
gemm_hmma_kernel(const float* __restrict__ A1,
                 const float* __restrict__ A2,
                 const float* __restrict__ B1,
                 const float* __restrict__ B2,
                 const float* __restrict__ bias1,
                 uint32_t* __restrict__ C1,
                 uint32_t* __restrict__ C2,
                 int M1, int M2)
{
    extern __shared__ uint32_t gsm[];
    uint32_t* sA = gsm;                 // [64][132]
    uint32_t* sB = gsm + 64 * GASTR;    // [128][132]

    const int tid  = threadIdx.x;
    const int wid  = tid >> 5;
    const int lane = tid & 31;
    const int N = H_;

    const float* A; const float* Bm; const float* bias; uint32_t* C;
    int M, mb;
    if (blockIdx.y < NB1) {
        A = A1; Bm = B1; bias = bias1; C = C1; M = M1; mb = blockIdx.y * 64;
    } else {
        A = A2; Bm = B2; bias = nullptr; C = C2; M = M2; mb = (blockIdx.y - NB1) * 64;
    }
    const int nb = blockIdx.x * 128;

    // stage A: 64 rows x 64 float4 (8 per thread)
    for (int i = tid; i < 64 * 64; i += 512) {
        int r  = i >> 6;
        int k4 = i & 63;
        int gm = mb + r;
        float4 v = make_float4(0.f, 0.f, 0.f, 0.f);
        if (gm < M) v = *(const float4*)(A + (size_t)gm * 256 + k4 * 4);
        sA[r * GASTR + k4 * 2]     = pack_bf16x2(v.x, v.y);
        sA[r * GASTR + k4 * 2 + 1] = pack_bf16x2(v.z, v.w);
    }
    // stage B: 128 k2 x 32 n4-groups (8 per thread)
    for (int i = tid; i < 128 * 32; i += 512) {
        int k2 = i >> 5;
        int n4 = (i & 31) * 4;
        const float* p0 = Bm + (size_t)(2 * k2) * N + nb + n4;
        float4 r0 = *(const float4*)p0;
        float4 r1 = *(const float4*)(p0 + N);
        sB[(n4 + 0) * GASTR + k2] = pack_bf16x2(r0.x, r1.x);
        sB[(n4 + 1) * GASTR + k2] = pack_bf16x2(r0.y, r1.y);
        sB[(n4 + 2) * GASTR + k2] = pack_bf16x2(r0.z, r1.z);
        sB[(n4 + 3) * GASTR + k2] = pack_bf16x2(r0.w, r1.w);
    }
    __syncthreads();

    const int gr = lane >> 2;
    const int c  = lane & 3;
    const int mrow = (wid & 3) * 16;
    const int nq   = (wid >> 2) * 4;      // n-tile base: 0,4,8,12
    const uint32_t* pa  = sA + (mrow + gr) * GASTR;
    const uint32_t* pa8 = pa + 8 * GASTR;
    const uint32_t* pbn = sB + gr * GASTR + nq * 8 * GASTR;

    float d0[4], d1[4], d2[4], d3[4];
    #pragma unroll
    for (int nt = 0; nt < 4; nt++) { d0[nt] = d1[nt] = d2[nt] = d3[nt] = 0.f; }

    #pragma unroll 4
    for (int ch = 0; ch < 16; ch++) {
        int k2b = ch * 8;
        uint32_t a0 = pa[k2b + c];
        uint32_t a1 = pa8[k2b + c];
        uint32_t a2 = pa[k2b + 4 + c];
        uint32_t a3 = pa8[k2b + 4 + c];
        #pragma unroll
        for (int nt = 0; nt < 4; nt++) {
            uint32_t b0 = pbn[nt * 8 * GASTR + k2b + c];
            uint32_t b1 = pbn[nt * 8 * GASTR + k2b + 4 + c];
            mma_bf16(d0[nt], d1[nt], d2[nt], d3[nt], a0, a1, a2, a3, b0, b1);
        }
    }

    int gm0 = mb + mrow + gr;
    int gm1 = gm0 + 8;
    #pragma unroll
    for (int nt = 0; nt < 4; nt++) {
        int gn = nb + (nq + nt) * 8 + 2 * c;        // even
        float bb0 = bias ? bias[gn]     : 0.f;
        float bb1 = bias ? bias[gn + 1] : 0.f;
        if (gm0 < M) C[(size_t)gm0 * H2_ + (gn >> 1)] = pack_bf16x2(d0[nt] + bb0, d1[nt] + bb1);
        if (gm1 < M) C[(size_t)gm1 * H2_ + (gn >> 1)] = pack_bf16x2(d2[nt] + bb0, d3[nt] + bb1);
    }
}

// ---------------------------------------------------------------------------
// HMMA joint kernel — persistent multi-tile + bf16 F/G (pre-packed in gmem).
// Grid (17, 8), 512 threads. Staging is pure uint4 copies now.
// ---------------------------------------------------------------------------
__global__ void __launch_bounds__(512)
joint_hmma_kernel(const float* __restrict__ Wp,
                  const float* __restrict__ bp,
                  const int*  __restrict__ targets)
{
    extern __shared__ char smraw[];
    uint32_t* sGh = (uint32_t*)(smraw + SM_G);    // [64][260] bf16x2 pairs
    uint32_t* sFh = (uint32_t*)(smraw + SM_F);    // [8][260]
    uint32_t* sBf = (uint32_t*)(smraw + SM_BF);
    float*    sD  = (float*)(smraw + SM_D);
    float*    sBp = (float*)(smraw + SM_BP);

    const int b    = blockIdx.y;
    const int tid  = threadIdx.x;
    const int wid  = tid >> 5;
    const int lane = tid & 31;

    const uint4* Gb4 = (const uint4*)(g_G + (size_t)b * U1_ * H2_);

    if (tid < V_) sBp[tid] = bp[tid];

    // stage G once: 61 rows x 64 uint4 (rows 61..63 zero)
    for (int i = tid; i < 64 * 64; i += 512) {
        int r  = i >> 6;
        int q4 = i & 63;
        uint4 v = make_uint4(0u, 0u, 0u, 0u);
        if (r < U1_) v = Gb4[r * 64 + q4];
        *(uint4*)&sGh[r * GSTRH + q4 * 4] = v;
    }
    // stage Wp fragments once
    for (int i = tid; i < 32 * 4 * 32; i += 512) {
        int ch = i >> 7;
        int nt = (i >> 5) & 3;
        int l  = i & 31;
        int kA = ch * 16 + 2 * (l & 3);
        int n  = nt * 8 + (l >> 2);
        uint32_t b0 = 0, b1 = 0;
        if (n < V_) {
            b0 = pack_bf16x2(Wp[(size_t)kA * V_ + n],       Wp[(size_t)(kA + 1) * V_ + n]);
            b1 = pack_bf16x2(Wp[(size_t)(kA + 8) * V_ + n], Wp[(size_t)(kA + 9) * V_ + n]);
        }
        sBf[(size_t)i * 2 + 0] = b0;
        sBf[(size_t)i * 2 + 1] = b1;
    }

    const int s    = wid & 3;
    const int tsub = wid >> 2;            // 0..3
    const int u0   = s * 16;
    const int gr    = lane >> 2;
    const int c4    = lane & 3;

    const uint32_t* gA = sGh + (u0 + gr) * GSTRH;
    const uint32_t* gB = gA + 8 * GSTRH;
    float* sDw = sD + wid * (16 * DSTR);

    for (int tt = 0; tt < 3; tt++) {
        const int tile = blockIdx.x + tt * JGX;
        if (tile >= JTILES) break;
        const int tbase = tile * 8;
        const uint4* Fb4 = (const uint4*)(g_F + (size_t)(b * T_ + tbase) * H2_);

        __syncthreads();   // previous tile's readers done before overwriting sF
        {
            int i = tid;   // 8 rows x 64 uint4 = 512 — exactly one per thread
            int r  = i >> 6;
            int q4 = i & 63;
            *(uint4*)&sFh[r * GSTRH + q4 * 4] = Fb4[r * 64 + q4];
        }
        __syncthreads();

        #pragma unroll 1
        for (int it = 0; it < 2; it++) {
            const int tloc = tsub * 2 + it;
            const uint32_t* fR = sFh + tloc * GSTRH;

            float d0[4], d1[4], d2[4], d3[4];
            #pragma unroll
            for (int nt = 0; nt < 4; nt++) { d0[nt] = d1[nt] = d2[nt] = d3[nt] = 0.f; }

            #pragma unroll 2
            for (int ch = 0; ch < 32; ch++) {
                int idx = ch * 8 + c4;
                uint32_t fv0 = fR[idx];
                uint32_t fv1 = fR[idx + 4];
                uint32_t a0 = tanh2_bf16(hadd2_bf16(fv0, gA[idx]));
                uint32_t a1 = tanh2_bf16(hadd2_bf16(fv0, gB[idx]));
                uint32_t a2 = tanh2_bf16(hadd2_bf16(fv1, gA[idx + 4]));
                uint32_t a3 = tanh2_bf16(hadd2_bf16(fv1, gB[idx + 4]));
                const uint32_t* bf = sBf + (size_t)(ch * 4) * 64 + lane * 2;
                #pragma unroll
                for (int nt = 0; nt < 4; nt++) {
                    uint32_t bb0 = bf[nt * 64 + 0];
                    uint32_t bb1 = bf[nt * 64 + 1];
                    mma_bf16(d0[nt], d1[nt], d2[nt], d3[nt], a0, a1, a2, a3, bb0, bb1);
                }
            }

            const int cbase = c4 * 2;
            #pragma unroll
            for (int nt = 0; nt < 4; nt++) {
                int cc = nt * 8 + cbase;
                *(float2*)&sDw[gr * DSTR + cc]       = make_float2(d0[nt], d1[nt]);
                *(float2*)&sDw[(gr + 8) * DSTR + cc] = make_float2(d2[nt], d3[nt]);
            }
            __syncwarp();

            if (lane < 16) {
                int u = u0 + lane;
                if (u < U1_) {
                    int t = tbase + tloc;
                    float logits[V_];
                    float m = -1e30f;
                    #pragma unroll
                    for (int v = 0; v < V_; v++) {
                        logits[v] = sDw[lane * DSTR + v] + sBp[v];
                        m = fmaxf(m, logits[v]);
                    }
                    float ssum = 0.f;
                    #pragma unroll
                    for (int v = 0; v < V_; v++) ssum += fast_ex2((logits[v] - m) * LOG2E);
                    float lse = m + fast_lg2(ssum) * LN2;

                    int tgt = (u < U_) ? targets[b * U_ + u] : 0;
                    float lv = logits[0];
                    #pragma unroll
                    for (int v = 1; v < V_; v++)
                        if (v == tgt) lv = logits[v];

                    size_t idx2 = (size_t)(b * T_ + t) * U1_ + u;
                    g_blank[idx2] = logits[BLANK_] - lse;
                    if (u < U_) g_lab[idx2] = lv - lse;
                }
            }
            __syncwarp();
        }
    }
}

// ---------------------------------------------------------------------------
// Forward DP (unchanged).
// ---------------------------------------------------------------------------
__global__ void dp_kernel(const int* __restrict__ t_lens,
                          const int* __restrict__ u_lens,
                          float* __restrict__ out)
{
    extern __shared__ float sm[];
    float* sB = sm;
    float* sL = sm + T_ * U1_;

    int b   = blockIdx.x;
    int tid = threadIdx.x;

    const int Tl = t_lens[b], Ul = u_lens[b];
    const int dcap = (Tl - 1) + Ul;

    const float4* srcB = (const float4*)(g_blank + (size_t)b * T_ * U1_);
    const float4* srcL = (const float4*)(g_lab   + (size_t)b * T_ * U1_);
    const int nrows = min(T_, dcap + 2);
    const int n4 = (nrows * U1_ + 3) / 4;
    for (int i = tid; i < n4; i += 1024) {
        float4 vb = srcB[i];
        float4 vl = srcL[i];
        vb.x *= LOG2E; vb.y *= LOG2E; vb.z *= LOG2E; vb.w *= LOG2E;
        vl.x *= LOG2E; vl.y *= LOG2E; vl.z *= LOG2E; vl.w *= LOG2E;
        ((float4*)sB)[i] = vb;
        ((float4*)sL)[i] = vl;
    }
    __syncthreads();
    if (tid >= 32) return;

    const int lane = tid;
    const bool cap_lo = (Ul < 32) && (lane == Ul);
    const bool cap_hi = (Ul >= 32) && (lane == Ul - 32);
    const int srcl = (lane + 31) & 31;

    const int u_lo = lane;
    const int u_hi = lane + 32;
    const int ulo_m1 = max(u_lo - 1, 0);
    const int uhi_c  = min(u_hi, U1_ - 1);
    const int uhi_m1 = min(u_hi - 1, U1_ - 1);

    float a_lo = (lane == 0) ? 0.f : NEGF;
    float a_hi = NEGF;
    float res  = 0.f;

    for (int d = 1; d <= 63; d++) {
        float p_lo = __shfl_up_sync(0xffffffffu, a_lo, 1);
        p_lo = (lane == 0) ? NEGF : p_lo;
        float yh   = (lane == 31) ? a_lo : a_hi;
        float p_hi = __shfl_sync(0xffffffffu, yh, srcl);

        int t  = d - u_lo;
        int i1 = min(max(t - 1, 0), T_ - 1);
        int i2 = min(max(t, 0), T_ - 1);
        float v1 = a_lo + sB[i1 * U1_ + u_lo];
        float v2 = p_lo + sL[i2 * U1_ + ulo_m1];
        float mx = fmaxf(v1, v2), mn = fminf(v1, v2);
        a_lo = mx + fast_lg2(1.f + fast_ex2(mn - mx));

        int th = d - u_hi;
        int j1 = min(max(th - 1, 0), T_ - 1);
        int j2 = min(max(th, 0), T_ - 1);
        float w1 = a_hi + sB[j1 * U1_ + uhi_c];
        float w2 = p_hi + sL[j2 * U1_ + uhi_m1];
        float mxh = fmaxf(w1, w2), mnh = fminf(w1, w2);
        a_hi = mxh + fast_lg2(1.f + fast_ex2(mnh - mxh));
    }

    {
        const int d2end = min(399, dcap);
        int ob_lo = (63 - u_lo) * U1_ + u_lo;
        int ol_lo = (64 - u_lo) * U1_ + ulo_m1;
        int ob_hi = (63 - u_hi) * U1_ + uhi_c;
        int ol_hi = (64 - u_hi) * U1_ + uhi_m1;

        float Blo = sB[ob_lo], Llo = sL[ol_lo];
        float Bhi = sB[ob_hi], Lhi = sL[ol_hi];

        #pragma unroll 2
        for (int d = 64; d <= d2end; d++) {
            ob_lo += U1_; ol_lo += U1_; ob_hi += U1_; ol_hi += U1_;
            float nBlo = sB[ob_lo];
            float nLlo = sL[ol_lo];
            float nBhi = sB[ob_hi];
            float nLhi = sL[ol_hi];

            float p_lo = __shfl_up_sync(0xffffffffu, a_lo, 1);
            p_lo = (lane == 0) ? NEGF : p_lo;
            float yh   = (lane == 31) ? a_lo : a_hi;
            float p_hi = __shfl_sync(0xffffffffu, yh, srcl);

            float v1 = a_lo + Blo;
            float v2 = p_lo + Llo;
            float mx = fmaxf(v1, v2), mn = fminf(v1, v2);
            float n_lo = mx + fast_lg2(1.f + fast_ex2(mn - mx));

            float w1 = a_hi + Bhi;
            float w2 = p_hi + Lhi;
            float mxh = fmaxf(w1, w2), mnh = fminf(w1, w2);
            float n_hi = mxh + fast_lg2(1.f + fast_ex2(mnh - mxh));

            bool hit = (d == dcap);
            res = (hit && cap_lo) ? n_lo : res;
            res = (hit && cap_hi) ? n_hi : res;
            a_lo = n_lo;
            a_hi = n_hi;
            Blo = nBlo; Llo = nLlo; Bhi = nBhi; Lhi = nLhi;
        }
    }

    for (int d = 400; d <= dcap; d++) {
        float p_lo = __shfl_up_sync(0xffffffffu, a_lo, 1);
        p_lo = (lane == 0) ? NEGF : p_lo;
        float yh   = (lane == 31) ? a_lo : a_hi;
        float p_hi = __shfl_sync(0xffffffffu, yh, srcl);

        int t  = d - u_lo;
        int i1 = min(max(t - 1, 0), T_ - 1);
        int i2 = min(max(t, 0), T_ - 1);
        float v1 = a_lo + sB[i1 * U1_ + u_lo];
        float v2 = p_lo + sL[i2 * U1_ + ulo_m1];
        float mx = fmaxf(v1, v2), mn = fminf(v1, v2);
        float n_lo = mx + fast_lg2(1.f + fast_ex2(mn - mx));

        int th = d - u_hi;
        int j1 = min(max(th - 1, 0), T_ - 1);
        int j2 = min(max(th, 0), T_ - 1);
        float w1 = a_hi + sB[j1 * U1_ + uhi_c];
        float w2 = p_hi + sL[j2 * U1_ + uhi_m1];
        float mxh = fmaxf(w1, w2), mnh = fminf(w1, w2);
        float n_hi = mxh + fast_lg2(1.f + fast_ex2(mnh - mxh));

        bool hit = (d == dcap);
        res = (hit && cap_lo) ? n_lo : res;
        res = (hit && cap_hi) ? n_hi : res;
        a_lo = n_lo;
        a_hi = n_hi;
    }

    if (cap_lo || cap_hi) {
        float blank_fin = g_blank[(size_t)b * T_ * U1_ + (size_t)(Tl - 1) * U1_ + Ul];
        out[b] = -(res * LN2 + blank_fin);
    }
}

// ---------------------------------------------------------------------------
extern "C" void kernel_launch(void* const* d_in, const int* in_sizes, int n_in,
                              void* d_out, int out_size)
{
    const float* enc     = (const float*)d_in[0];
    const float* dec     = (const float*)d_in[1];
    const float* We      = (const float*)d_in[2];
    const float* Wd      = (const float*)d_in[3];
    const float* bf      = (const float*)d_in[4];
    const float* Wp      = (const float*)d_in[5];
    const float* bp      = (const float*)d_in[6];
    const int*   targets = (const int*)d_in[7];
    const int*   t_lens  = (const int*)d_in[8];
    const int*   u_lens  = (const int*)d_in[9];
    float* out = (float*)d_out;

    uint32_t *pF = nullptr, *pG = nullptr;
    cudaGetSymbolAddress((void**)&pF, g_F);
    cudaGetSymbolAddress((void**)&pG, g_G);

    static bool attr_set = false;
    if (!attr_set) {
        cudaFuncSetAttribute(dp_kernel,
                             cudaFuncAttributeMaxDynamicSharedMemorySize, DP_SMEM);
        cudaFuncSetAttribute(joint_hmma_kernel,
                             cudaFuncAttributeMaxDynamicSharedMemorySize, JSMEM);
        cudaFuncSetAttribute(gemm_hmma_kernel,
                             cudaFuncAttributeMaxDynamicSharedMemorySize, GEMM_SMEM);
        attr_set = true;
    }

    gemm_hmma_kernel<<<dim3(H_ / 128, NB1 + NB2), 512, GEMM_SMEM>>>(
        enc, dec, We, Wd, bf, pF, pG, B_ * T_, B_ * U1_);
    joint_hmma_kernel<<<dim3(JGX, B_), 512, JSMEM>>>(Wp, bp, targets);
    dp_kernel<<<B_, 1024, DP_SMEM>>>(t_lens, u_lens, out);
}

// round 17
// speedup vs baseline: 1.5904x; 1.0251x over previous
#include <cuda_runtime.h>
#include <cuda_bf16.h>
#include <cstdint>

#define B_    8
#define T_    400
#define U_    60
#define U1_   61
#define E_    256
#define H_    512
#define H2_   256                             // H/2 bf16x2 pairs per row
#define V_    28
#define BLANK_ 27
#define NEGF  (-1e30f)
#define LOG2E 1.4426950408889634f
#define LN2   0.6931471805599453f

// joint smem layout (bytes) — bf16 F/G version
#define GSTRH  260                            // G/F row stride in u32 (256 + 4 pad)
#define DSTR   34
#define SM_G   0                              // 64*260*4  = 66560
#define SM_F   66560                          // 8*260*4   = 8320
#define SM_BF  74880                          // 32*4*32*8 = 32768
#define SM_D   107648                         // 16*16*34*4= 34816
#define SM_BP  142464                         // 128
#define JSMEM  142592

// joint tiling: 50 t-tiles of 8, grid.x=17, each block does <=3 tiles
#define JTILES 50
#define JGX    17

// gemm smem: sA 64x132 u32 + sB 64x132 u32  (64x64 tile — R14 config)
#define GASTR  132
#define GEMM_SMEM (2 * 64 * GASTR * 4)
#define NB1    50
#define NB2    8

// dp smem: 2*T*U1 floats + 128 pad (prefetch overrun)
#define DP_SMEM ((2 * T_ * U1_ + 128) * 4)

// Scratch (no cudaMalloc allowed) — F/G stored as packed bf16x2
__device__ uint32_t g_F[B_*T_*H2_];
__device__ uint32_t g_G[B_*U1_*H2_];
__device__ float g_blank[B_*T_*U1_];
__device__ float g_lab[B_*T_*U1_];

__device__ __forceinline__ float fast_ex2(float x) {
    float y; asm("ex2.approx.f32 %0, %1;" : "=f"(y) : "f"(x)); return y;
}
__device__ __forceinline__ float fast_lg2(float x) {
    float y; asm("lg2.approx.f32 %0, %1;" : "=f"(y) : "f"(x)); return y;
}
__device__ __forceinline__ uint32_t pack_bf16x2(float lo, float hi) {
    uint32_t r;
    asm("cvt.rn.bf16x2.f32 %0, %1, %2;" : "=r"(r) : "f"(hi), "f"(lo));
    return r;
}
__device__ __forceinline__ uint32_t hadd2_bf16(uint32_t a, uint32_t b) {
    uint32_t d;
    asm("add.rn.bf16x2 %0, %1, %2;" : "=r"(d) : "r"(a), "r"(b));
    return d;
}
__device__ __forceinline__ uint32_t tanh2_bf16(uint32_t a) {
    uint32_t d;
    asm("tanh.approx.bf16x2 %0, %1;" : "=r"(d) : "r"(a));
    return d;
}
__device__ __forceinline__ void mma_bf16(float& d0, float& d1, float& d2, float& d3,
                                         uint32_t a0, uint32_t a1, uint32_t a2, uint32_t a3,
                                         uint32_t b0, uint32_t b1) {
    asm("mma.sync.aligned.m16n8k16.row.col.f32.bf16.bf16.f32 "
        "{%0,%1,%2,%3}, {%4,%5,%6,%7}, {%8,%9}, {%0,%1,%2,%3};"
        : "+f"(d0), "+f"(d1), "+f"(d2), "+f"(d3)
        : "r"(a0), "r"(a1), "r"(a2), "r"(a3), "r"(b0), "r"(b1));
}

// ---------------------------------------------------------------------------
// Merged bf16 HMMA GEMM, 512 threads, tile 64m x 64n (R14 config), bf16x2 out.
// grid (8, 58). Warp w: m-strip (w&3)*16, n-quarter (w>>2) -> 2 n-tiles.
// ---------------------------------------------------------------------------
__global__ void __launch_bounds__(512)
gemm_hmma_kernel(const float* __restrict__ A1,
                 const float* __restrict__ A2,
                 const float* __restrict__ B1,
                 const float* __restrict__ B2,
                 const float* __restrict__ bias1,
                 uint32_t* __restrict__ C1,
                 uint32_t* __restrict__ C2,
                 int M1, int M2)
{
    extern __shared__ uint32_t gsm[];
    uint32_t* sA = gsm;                 // [64][132]
    uint32_t* sB = gsm + 64 * GASTR;    // [64][132]

    const int tid  = threadIdx.x;
    const int wid  = tid >> 5;
    const int lane = tid & 31;
    const int N = H_;

    const float* A; const float* Bm; const float* bias; uint32_t* C;
    int M, mb;
    if (blockIdx.y < NB1) {
        A = A1; Bm = B1; bias = bias1; C = C1; M = M1; mb = blockIdx.y * 64;
    } else {
        A = A2; Bm = B2; bias = nullptr; C = C2; M = M2; mb = (blockIdx.y - NB1) * 64;
    }
    const int nb = blockIdx.x * 64;

    for (int i = tid; i < 64 * 64; i += 512) {
        int r  = i >> 6;
        int k4 = i & 63;
        int gm = mb + r;
        float4 v = make_float4(0.f, 0.f, 0.f, 0.f);
        if (gm < M) v = *(const float4*)(A + (size_t)gm * 256 + k4 * 4);
        sA[r * GASTR + k4 * 2]     = pack_bf16x2(v.x, v.y);
        sA[r * GASTR + k4 * 2 + 1] = pack_bf16x2(v.z, v.w);
    }
    for (int i = tid; i < 128 * 16; i += 512) {
        int k2 = i >> 4;
        int n4 = (i & 15) * 4;
        const float* p0 = Bm + (size_t)(2 * k2) * N + nb + n4;
        float4 r0 = *(const float4*)p0;
        float4 r1 = *(const float4*)(p0 + N);
        sB[(n4 + 0) * GASTR + k2] = pack_bf16x2(r0.x, r1.x);
        sB[(n4 + 1) * GASTR + k2] = pack_bf16x2(r0.y, r1.y);
        sB[(n4 + 2) * GASTR + k2] = pack_bf16x2(r0.z, r1.z);
        sB[(n4 + 3) * GASTR + k2] = pack_bf16x2(r0.w, r1.w);
    }
    __syncthreads();

    const int gr = lane >> 2;
    const int c  = lane & 3;
    const int mrow = (wid & 3) * 16;
    const int nq   = (wid >> 2) * 2;      // n-tile base: 0,2,4,6
    const uint32_t* pa  = sA + (mrow + gr) * GASTR;
    const uint32_t* pa8 = pa + 8 * GASTR;
    const uint32_t* pbn = sB + gr * GASTR + nq * 8 * GASTR;

    float d0[2], d1[2], d2[2], d3[2];
    #pragma unroll
    for (int nt = 0; nt < 2; nt++) { d0[nt] = d1[nt] = d2[nt] = d3[nt] = 0.f; }

    #pragma unroll 4
    for (int ch = 0; ch < 16; ch++) {
        int k2b = ch * 8;
        uint32_t a0 = pa[k2b + c];
        uint32_t a1 = pa8[k2b + c];
        uint32_t a2 = pa[k2b + 4 + c];
        uint32_t a3 = pa8[k2b + 4 + c];
        #pragma unroll
        for (int nt = 0; nt < 2; nt++) {
            uint32_t b0 = pbn[nt * 8 * GASTR + k2b + c];
            uint32_t b1 = pbn[nt * 8 * GASTR + k2b + 4 + c];
            mma_bf16(d0[nt], d1[nt], d2[nt], d3[nt], a0, a1, a2, a3, b0, b1);
        }
    }

    int gm0 = mb + mrow + gr;
    int gm1 = gm0 + 8;
    #pragma unroll
    for (int nt = 0; nt < 2; nt++) {
        int gn = nb + (nq + nt) * 8 + 2 * c;        // even
        float bb0 = bias ? bias[gn]     : 0.f;
        float bb1 = bias ? bias[gn + 1] : 0.f;
        if (gm0 < M) C[(size_t)gm0 * H2_ + (gn >> 1)] = pack_bf16x2(d0[nt] + bb0, d1[nt] + bb1);
        if (gm1 < M) C[(size_t)gm1 * H2_ + (gn >> 1)] = pack_bf16x2(d2[nt] + bb0, d3[nt] + bb1);
    }
}

// ---------------------------------------------------------------------------
// HMMA joint kernel — persistent multi-tile + bf16 F/G (pre-packed in gmem).
// Grid (17, 8), 512 threads. Staging is pure uint4 copies.
// ---------------------------------------------------------------------------
__global__ void __launch_bounds__(512)
joint_hmma_kernel(const float* __restrict__ Wp,
                  const float* __restrict__ bp,
                  const int*  __restrict__ targets)
{
    extern __shared__ char smraw[];
    uint32_t* sGh = (uint32_t*)(smraw + SM_G);    // [64][260] bf16x2 pairs
    uint32_t* sFh = (uint32_t*)(smraw + SM_F);    // [8][260]
    uint32_t* sBf = (uint32_t*)(smraw + SM_BF);
    float*    sD  = (float*)(smraw + SM_D);
    float*    sBp = (float*)(smraw + SM_BP);

    const int b    = blockIdx.y;
    const int tid  = threadIdx.x;
    const int wid  = tid >> 5;
    const int lane = tid & 31;

    const uint4* Gb4 = (const uint4*)(g_G + (size_t)b * U1_ * H2_);

    if (tid < V_) sBp[tid] = bp[tid];

    // stage G once: 61 rows x 64 uint4 (rows 61..63 zero)
    for (int i = tid; i < 64 * 64; i += 512) {
        int r  = i >> 6;
        int q4 = i & 63;
        uint4 v = make_uint4(0u, 0u, 0u, 0u);
        if (r < U1_) v = Gb4[r * 64 + q4];
        *(uint4*)&sGh[r * GSTRH + q4 * 4] = v;
    }
    // stage Wp fragments once
    for (int i = tid; i < 32 * 4 * 32; i += 512) {
        int ch = i >> 7;
        int nt = (i >> 5) & 3;
        int l  = i & 31;
        int kA = ch * 16 + 2 * (l & 3);
        int n  = nt * 8 + (l >> 2);
        uint32_t b0 = 0, b1 = 0;
        if (n < V_) {
            b0 = pack_bf16x2(Wp[(size_t)kA * V_ + n],       Wp[(size_t)(kA + 1) * V_ + n]);
            b1 = pack_bf16x2(Wp[(size_t)(kA + 8) * V_ + n], Wp[(size_t)(kA + 9) * V_ + n]);
        }
        sBf[(size_t)i * 2 + 0] = b0;
        sBf[(size_t)i * 2 + 1] = b1;
    }

    const int s    = wid & 3;
    const int tsub = wid >> 2;            // 0..3
    const int u0   = s * 16;
    const int gr    = lane >> 2;
    const int c4    = lane & 3;

    const uint32_t* gA = sGh + (u0 + gr) * GSTRH;
    const uint32_t* gB = gA + 8 * GSTRH;
    float* sDw = sD + wid * (16 * DSTR);

    for (int tt = 0; tt < 3; tt++) {
        const int tile = blockIdx.x + tt * JGX;
        if (tile >= JTILES) break;
        const int tbase = tile * 8;
        const uint4* Fb4 = (const uint4*)(g_F + (size_t)(b * T_ + tbase) * H2_);

        __syncthreads();   // previous tile's readers done before overwriting sF
        {
            int i = tid;   // 8 rows x 64 uint4 = 512 — exactly one per thread
            int r  = i >> 6;
            int q4 = i & 63;
            *(uint4*)&sFh[r * GSTRH + q4 * 4] = Fb4[r * 64 + q4];
        }
        __syncthreads();

        #pragma unroll 1
        for (int it = 0; it < 2; it++) {
            const int tloc = tsub * 2 + it;
            const uint32_t* fR = sFh + tloc * GSTRH;

            float d0[4], d1[4], d2[4], d3[4];
            #pragma unroll
            for (int nt = 0; nt < 4; nt++) { d0[nt] = d1[nt] = d2[nt] = d3[nt] = 0.f; }

            #pragma unroll 2
            for (int ch = 0; ch < 32; ch++) {
                int idx = ch * 8 + c4;
                uint32_t fv0 = fR[idx];
                uint32_t fv1 = fR[idx + 4];
                uint32_t a0 = tanh2_bf16(hadd2_bf16(fv0, gA[idx]));
                uint32_t a1 = tanh2_bf16(hadd2_bf16(fv0, gB[idx]));
                uint32_t a2 = tanh2_bf16(hadd2_bf16(fv1, gA[idx + 4]));
                uint32_t a3 = tanh2_bf16(hadd2_bf16(fv1, gB[idx + 4]));
                const uint32_t* bf = sBf + (size_t)(ch * 4) * 64 + lane * 2;
                #pragma unroll
                for (int nt = 0; nt < 4; nt++) {
                    uint32_t bb0 = bf[nt * 64 + 0];
                    uint32_t bb1 = bf[nt * 64 + 1];
                    mma_bf16(d0[nt], d1[nt], d2[nt], d3[nt], a0, a1, a2, a3, bb0, bb1);
                }
            }

            const int cbase = c4 * 2;
            #pragma unroll
            for (int nt = 0; nt < 4; nt++) {
                int cc = nt * 8 + cbase;
                *(float2*)&sDw[gr * DSTR + cc]       = make_float2(d0[nt], d1[nt]);
                *(float2*)&sDw[(gr + 8) * DSTR + cc] = make_float2(d2[nt], d3[nt]);
            }
            __syncwarp();

            if (lane < 16) {
                int u = u0 + lane;
                if (u < U1_) {
                    int t = tbase + tloc;
                    float logits[V_];
                    float m = -1e30f;
                    #pragma unroll
                    for (int v = 0; v < V_; v++) {
                        logits[v] = sDw[lane * DSTR + v] + sBp[v];
                        m = fmaxf(m, logits[v]);
                    }
                    float ssum = 0.f;
                    #pragma unroll
                    for (int v = 0; v < V_; v++) ssum += fast_ex2((logits[v] - m) * LOG2E);
                    float lse = m + fast_lg2(ssum) * LN2;

                    int tgt = (u < U_) ? targets[b * U_ + u] : 0;
                    float lv = logits[0];
                    #pragma unroll
                    for (int v = 1; v < V_; v++)
                        if (v == tgt) lv = logits[v];

                    size_t idx2 = (size_t)(b * T_ + t) * U1_ + u;
                    g_blank[idx2] = logits[BLANK_] - lse;
                    if (u < U_) g_lab[idx2] = lv - lse;
                }
            }
            __syncwarp();
        }
    }
}

// ---------------------------------------------------------------------------
// Forward DP (unchanged).
// ---------------------------------------------------------------------------
__global__ void dp_kernel(const int* __restrict__ t_lens,
                          const int* __restrict__ u_lens,
                          float* __restrict__ out)
{
    extern __shared__ float sm[];
    float* sB = sm;
    float* sL = sm + T_ * U1_;

    int b   = blockIdx.x;
    int tid = threadIdx.x;

    const int Tl = t_lens[b], Ul = u_lens[b];
    const int dcap = (Tl - 1) + Ul;

    const float4* srcB = (const float4*)(g_blank + (size_t)b * T_ * U1_);
    const float4* srcL = (const float4*)(g_lab   + (size_t)b * T_ * U1_);
    const int nrows = min(T_, dcap + 2);
    const int n4 = (nrows * U1_ + 3) / 4;
    for (int i = tid; i < n4; i += 1024) {
        float4 vb = srcB[i];
        float4 vl = srcL[i];
        vb.x *= LOG2E; vb.y *= LOG2E; vb.z *= LOG2E; vb.w *= LOG2E;
        vl.x *= LOG2E; vl.y *= LOG2E; vl.z *= LOG2E; vl.w *= LOG2E;
        ((float4*)sB)[i] = vb;
        ((float4*)sL)[i] = vl;
    }
    __syncthreads();
    if (tid >= 32) return;

    const int lane = tid;
    const bool cap_lo = (Ul < 32) && (lane == Ul);
    const bool cap_hi = (Ul >= 32) && (lane == Ul - 32);
    const int srcl = (lane + 31) & 31;

    const int u_lo = lane;
    const int u_hi = lane + 32;
    const int ulo_m1 = max(u_lo - 1, 0);
    const int uhi_c  = min(u_hi, U1_ - 1);
    const int uhi_m1 = min(u_hi - 1, U1_ - 1);

    float a_lo = (lane == 0) ? 0.f : NEGF;
    float a_hi = NEGF;
    float res  = 0.f;

    for (int d = 1; d <= 63; d++) {
        float p_lo = __shfl_up_sync(0xffffffffu, a_lo, 1);
        p_lo = (lane == 0) ? NEGF : p_lo;
        float yh   = (lane == 31) ? a_lo : a_hi;
        float p_hi = __shfl_sync(0xffffffffu, yh, srcl);

        int t  = d - u_lo;
        int i1 = min(max(t - 1, 0), T_ - 1);
        int i2 = min(max(t, 0), T_ - 1);
        float v1 = a_lo + sB[i1 * U1_ + u_lo];
        float v2 = p_lo + sL[i2 * U1_ + ulo_m1];
        float mx = fmaxf(v1, v2), mn = fminf(v1, v2);
        a_lo = mx + fast_lg2(1.f + fast_ex2(mn - mx));

        int th = d - u_hi;
        int j1 = min(max(th - 1, 0), T_ - 1);
        int j2 = min(max(th, 0), T_ - 1);
        float w1 = a_hi + sB[j1 * U1_ + uhi_c];
        float w2 = p_hi + sL[j2 * U1_ + uhi_m1];
        float mxh = fmaxf(w1, w2), mnh = fminf(w1, w2);
        a_hi = mxh + fast_lg2(1.f + fast_ex2(mnh - mxh));
    }

    {
        const int d2end = min(399, dcap);
        int ob_lo = (63 - u_lo) * U1_ + u_lo;
        int ol_lo = (64 - u_lo) * U1_ + ulo_m1;
        int ob_hi = (63 - u_hi) * U1_ + uhi_c;
        int ol_hi = (64 - u_hi) * U1_ + uhi_m1;

        float Blo = sB[ob_lo], Llo = sL[ol_lo];
        float Bhi = sB[ob_hi], Lhi = sL[ol_hi];

        #pragma unroll 2
        for (int d = 64; d <= d2end; d++) {
            ob_lo += U1_; ol_lo += U1_; ob_hi += U1_; ol_hi += U1_;
            float nBlo = sB[ob_lo];
            float nLlo = sL[ol_lo];
            float nBhi = sB[ob_hi];
            float nLhi = sL[ol_hi];

            float p_lo = __shfl_up_sync(0xffffffffu, a_lo, 1);
            p_lo = (lane == 0) ? NEGF : p_lo;
            float yh   = (lane == 31) ? a_lo : a_hi;
            float p_hi = __shfl_sync(0xffffffffu, yh, srcl);

            float v1 = a_lo + Blo;
            float v2 = p_lo + Llo;
            float mx = fmaxf(v1, v2), mn = fminf(v1, v2);
            float n_lo = mx + fast_lg2(1.f + fast_ex2(mn - mx));

            float w1 = a_hi + Bhi;
            float w2 = p_hi + Lhi;
            float mxh = fmaxf(w1, w2), mnh = fminf(w1, w2);
            float n_hi = mxh + fast_lg2(1.f + fast_ex2(mnh - mxh));

            bool hit = (d == dcap);
            res = (hit && cap_lo) ? n_lo : res;
            res = (hit && cap_hi) ? n_hi : res;
            a_lo = n_lo;
            a_hi = n_hi;
            Blo = nBlo; Llo = nLlo; Bhi = nBhi; Lhi = nLhi;
        }
    }

    for (int d = 400; d <= dcap; d++) {
        float p_lo = __shfl_up_sync(0xffffffffu, a_lo, 1);
        p_lo = (lane == 0) ? NEGF : p_lo;
        float yh   = (lane == 31) ? a_lo : a_hi;
        float p_hi = __shfl_sync(0xffffffffu, yh, srcl);

        int t  = d - u_lo;
        int i1 = min(max(t - 1, 0), T_ - 1);
        int i2 = min(max(t, 0), T_ - 1);
        float v1 = a_lo + sB[i1 * U1_ + u_lo];
        float v2 = p_lo + sL[i2 * U1_ + ulo_m1];
        float mx = fmaxf(v1, v2), mn = fminf(v1, v2);
        float n_lo = mx + fast_lg2(1.f + fast_ex2(mn - mx));

        int th = d - u_hi;
        int j1 = min(max(th - 1, 0), T_ - 1);
        int j2 = min(max(th, 0), T_ - 1);
        float w1 = a_hi + sB[j1 * U1_ + uhi_c];
        float w2 = p_hi + sL[j2 * U1_ + uhi_m1];
        float mxh = fmaxf(w1, w2), mnh = fminf(w1, w2);
        float n_hi = mxh + fast_lg2(1.f + fast_ex2(mnh - mxh));

        bool hit = (d == dcap);
        res = (hit && cap_lo) ? n_lo : res;
        res = (hit && cap_hi) ? n_hi : res;
        a_lo = n_lo;
        a_hi = n_hi;
    }

    if (cap_lo || cap_hi) {
        float blank_fin = g_blank[(size_t)b * T_ * U1_ + (size_t)(Tl - 1) * U1_ + Ul];
        out[b] = -(res * LN2 + blank_fin);
    }
}

// ---------------------------------------------------------------------------
extern "C" void kernel_launch(void* const* d_in, const int* in_sizes, int n_in,
                              void* d_out, int out_size)
{
    const float* enc     = (const float*)d_in[0];
    const float* dec     = (const float*)d_in[1];
    const float* We      = (const float*)d_in[2];
    const float* Wd      = (const float*)d_in[3];
    const float* bf      = (const float*)d_in[4];
    const float* Wp      = (const float*)d_in[5];
    const float* bp      = (const float*)d_in[6];
    const int*   targets = (const int*)d_in[7];
    const int*   t_lens  = (const int*)d_in[8];
    const int*   u_lens  = (const int*)d_in[9];
    float* out = (float*)d_out;

    uint32_t *pF = nullptr, *pG = nullptr;
    cudaGetSymbolAddress((void**)&pF, g_F);
    cudaGetSymbolAddress((void**)&pG, g_G);

    static bool attr_set = false;
    if (!attr_set) {
        cudaFuncSetAttribute(dp_kernel,
                             cudaFuncAttributeMaxDynamicSharedMemorySize, DP_SMEM);
        cudaFuncSetAttribute(joint_hmma_kernel,
                             cudaFuncAttributeMaxDynamicSharedMemorySize, JSMEM);
        cudaFuncSetAttribute(gemm_hmma_kernel,
                             cudaFuncAttributeMaxDynamicSharedMemorySize, GEMM_SMEM);
        attr_set = true;
    }

    gemm_hmma_kernel<<<dim3(H_ / 64, NB1 + NB2), 512, GEMM_SMEM>>>(
        enc, dec, We, Wd, bf, pF, pG, B_ * T_, B_ * U1_);
    joint_hmma_kernel<<<dim3(JGX, B_), 512, JSMEM>>>(Wp, bp, targets);
    dp_kernel<<<B_, 1024, DP_SMEM>>>(t_lens, u_lens, out);
}